// round 8
// baseline (speedup 1.0000x reference)
#include <cuda_runtime.h>
#include <cuda_bf16.h>
#include <cstdint>

#define S_LEN 2048
#define HID 3072
#define NH 24
#define NKV 8
#define HD 128
#define OPSZ 5120
#define QK_COLS 4096
#define SCALING 0.08838834764831845f

// ---------------------------------------------------------------------------
// Scratch (__device__ globals; runtime allocation forbidden)
// ---------------------------------------------------------------------------
__device__ float g_qkv[(size_t)S_LEN * OPSZ];                                  // 42 MB
__device__ __nv_bfloat16 g_hidh [(size_t)S_LEN * HID],  g_hidl [(size_t)S_LEN * HID];
__device__ __nv_bfloat16 g_wqkvh[(size_t)OPSZ * HID],   g_wqkvl[(size_t)OPSZ * HID];
__device__ __nv_bfloat16 g_woh  [(size_t)HID * HID],    g_wol  [(size_t)HID * HID];
__device__ __nv_bfloat16 g_qkh  [(size_t)S_LEN * QK_COLS], g_qkl[(size_t)S_LEN * QK_COLS];
__device__ __nv_bfloat16 g_vTh  [(size_t)NKV * HD * S_LEN], g_vTl[(size_t)NKV * HD * S_LEN];
__device__ __nv_bfloat16 g_Ph   [(size_t)NH * S_LEN * S_LEN];                  // 201 MB
__device__ __nv_bfloat16 g_Pl   [(size_t)NH * S_LEN * S_LEN];                  // 201 MB
__device__ __nv_bfloat16 g_aoh  [(size_t)S_LEN * HID],  g_aol [(size_t)S_LEN * HID];

// ---------------------------------------------------------------------------
// helpers
// ---------------------------------------------------------------------------
__device__ __forceinline__ uint32_t smem_u32(const void* p) {
    uint32_t a;
    asm("{ .reg .u64 t; cvta.to.shared.u64 t, %1; cvt.u32.u64 %0, t; }"
        : "=r"(a) : "l"(p));
    return a;
}
__device__ __forceinline__ void ldm4(uint32_t* r, uint32_t addr) {
    asm volatile("ldmatrix.sync.aligned.m8n8.x4.shared.b16 {%0,%1,%2,%3}, [%4];"
        : "=r"(r[0]), "=r"(r[1]), "=r"(r[2]), "=r"(r[3]) : "r"(addr));
}
__device__ __forceinline__ void mma16816(float* c, const uint32_t* a,
                                         const uint32_t* b) {
    asm volatile(
        "mma.sync.aligned.m16n8k16.row.col.f32.bf16.bf16.f32 "
        "{%0,%1,%2,%3}, {%4,%5,%6,%7}, {%8,%9}, {%0,%1,%2,%3};"
        : "+f"(c[0]), "+f"(c[1]), "+f"(c[2]), "+f"(c[3])
        : "r"(a[0]), "r"(a[1]), "r"(a[2]), "r"(a[3]), "r"(b[0]), "r"(b[1]));
}
// pack two fp32 -> bf16x2 (lo half = a, hi half = b), round-to-nearest
__device__ __forceinline__ uint32_t pk2(float a, float b) {
    uint32_t r;
    asm("cvt.rn.bf16x2.f32 %0, %1, %2;" : "=r"(r) : "f"(b), "f"(a));
    return r;
}
#define CP16(dst, src) \
    asm volatile("cp.async.cg.shared.global [%0], [%1], 16;" \
                 :: "r"(dst), "l"(src) : "memory")
#define CP_COMMIT() asm volatile("cp.async.commit_group;" ::: "memory")
#define CP_WAIT1()  asm volatile("cp.async.wait_group 1;" ::: "memory")

// ---------------------------------------------------------------------------
// fp32 -> (bf16 hi, bf16 lo) elementwise split, 4 elems/thread
// ---------------------------------------------------------------------------
__global__ __launch_bounds__(256) void conv_split(
    const float* __restrict__ src, __nv_bfloat16* __restrict__ h,
    __nv_bfloat16* __restrict__ l, int n4)
{
    int i = blockIdx.x * 256 + threadIdx.x;
    if (i >= n4) return;
    float4 x = ((const float4*)src)[i];
    uint32_t p0 = pk2(x.x, x.y), p1 = pk2(x.z, x.w);
    float l0 = x.x - __uint_as_float(p0 << 16);
    float l1 = x.y - __uint_as_float(p0 & 0xffff0000u);
    float l2 = x.z - __uint_as_float(p1 << 16);
    float l3 = x.w - __uint_as_float(p1 & 0xffff0000u);
    uint2 hh; hh.x = p0; hh.y = p1;
    uint2 ll; ll.x = pk2(l0, l1); ll.y = pk2(l2, l3);
    ((uint2*)h)[i] = hh;
    ((uint2*)l)[i] = ll;
}

// ---------------------------------------------------------------------------
// Fused RoPE + split on Q/K columns (0..4095) of qkv. 4 elems/thread.
// ---------------------------------------------------------------------------
__global__ __launch_bounds__(256) void rope_split(
    const float* __restrict__ qkv, const float* __restrict__ cosb,
    const float* __restrict__ sinb,
    __nv_bfloat16* __restrict__ qh, __nv_bfloat16* __restrict__ ql)
{
    int idx = blockIdx.x * 256 + threadIdx.x;   // S_LEN * 1024
    int s = idx >> 10;
    int c = (idx & 1023) * 4;
    int d = c & 127;
    const float* row = qkv + (size_t)s * OPSZ;
    float4 x = *(const float4*)(row + c);
    if (d < 96) {
        float4 cc = *(const float4*)(cosb + s * 96 + d);
        float4 ss = *(const float4*)(sinb + s * 96 + d);
        if (d < 48) {
            float4 p = *(const float4*)(row + c + 48);
            x.x = x.x * cc.x - p.x * ss.x;
            x.y = x.y * cc.y - p.y * ss.y;
            x.z = x.z * cc.z - p.z * ss.z;
            x.w = x.w * cc.w - p.w * ss.w;
        } else {
            float4 p = *(const float4*)(row + c - 48);
            x.x = x.x * cc.x + p.x * ss.x;
            x.y = x.y * cc.y + p.y * ss.y;
            x.z = x.z * cc.z + p.z * ss.z;
            x.w = x.w * cc.w + p.w * ss.w;
        }
    }
    uint32_t p0 = pk2(x.x, x.y), p1 = pk2(x.z, x.w);
    float l0 = x.x - __uint_as_float(p0 << 16);
    float l1 = x.y - __uint_as_float(p0 & 0xffff0000u);
    float l2 = x.z - __uint_as_float(p1 << 16);
    float l3 = x.w - __uint_as_float(p1 & 0xffff0000u);
    uint2 hh; hh.x = p0; hh.y = p1;
    uint2 ll; ll.x = pk2(l0, l1); ll.y = pk2(l2, l3);
    size_t o = ((size_t)s * QK_COLS + c) >> 2;
    ((uint2*)qh)[o] = hh;
    ((uint2*)ql)[o] = ll;
}

// ---------------------------------------------------------------------------
// V transpose + split: vT[kv*HD+d][s] = qkv[s][4096+kv*HD+d], SMEM-tiled.
// ---------------------------------------------------------------------------
__global__ __launch_bounds__(256) void vsplit_T(
    const float* __restrict__ qkv,
    __nv_bfloat16* __restrict__ vh, __nv_bfloat16* __restrict__ vl)
{
    __shared__ float tile[32][33];
    const int t0 = blockIdx.x * 32;
    const int s0 = blockIdx.y * 32;
    const int tx = threadIdx.x, ty = threadIdx.y;   // (32, 8)
#pragma unroll
    for (int j = 0; j < 4; j++)
        tile[ty + 8 * j][tx] =
            qkv[(size_t)(s0 + ty + 8 * j) * OPSZ + 4096 + t0 + tx];
    __syncthreads();
#pragma unroll
    for (int j = 0; j < 4; j++) {
        float v = tile[tx][ty + 8 * j];
        __nv_bfloat16 hb = __float2bfloat16(v);
        size_t o = (size_t)(t0 + ty + 8 * j) * S_LEN + s0 + tx;
        vh[o] = hb;
        vl[o] = __float2bfloat16(v - __bfloat162float(hb));
    }
}

// ---------------------------------------------------------------------------
// Generic NT GEMM, bf16 hi/lo operands, compensated (3 HMMA per k16).
// C[M,N] = alpha * (Ah+Al)[M,K] * (Bh+Bl)[N,K]^T  (dropping AlBl term)
// 128x64 tile, 256 threads (8 warps, warp tile 32x32), KC=32,
// 2-stage cp.async double buffer, 80B SMEM row pitch, 3 CTAs/SM target.
// flags: 1 = causal tile skip, 2 = K limited to row0+128, 4 = split output.
// ---------------------------------------------------------------------------
#define KC 32
#define ATILE_B 10240u             // 128 rows * 80 B
#define BTILE_B 5120u              //  64 rows * 80 B
#define STAGE_B (2u * ATILE_B + 2u * BTILE_B)   // 30720
#define NSTAGE  2
#define GEMM_SMEM (NSTAGE * STAGE_B)            // 61440

__global__ __launch_bounds__(256, 3) void gemm_bf16(
    const __nv_bfloat16* __restrict__ Ah, const __nv_bfloat16* __restrict__ Al,
    int lda, long long sAz,
    const __nv_bfloat16* __restrict__ Bh, const __nv_bfloat16* __restrict__ Bl,
    int ldb, long long sBz, int kvdiv,
    float* __restrict__ Cf, __nv_bfloat16* __restrict__ Ch,
    __nv_bfloat16* __restrict__ Cl, int ldc, long long sCz,
    int K, float alpha, int flags)
{
    const int row0 = blockIdx.y << 7;
    const int col0 = blockIdx.x << 6;
    if ((flags & 1) && col0 >= row0 + 128) return;
    const int z = blockIdx.z;
    const size_t za = (size_t)z * sAz;
    const size_t zb = (size_t)(z / kvdiv) * sBz;
    const size_t zc = (size_t)z * sCz;
    Ah += za; Al += za; Bh += zb; Bl += zb;
    const int Keff = (flags & 2) ? ((K < row0 + 128) ? K : row0 + 128) : K;
    const int nCh  = Keff >> 5;

    extern __shared__ char smem[];
    const uint32_t base = smem_u32(smem);

    const int tid  = threadIdx.x;
    const int warp = tid >> 5;
    const int lane = tid & 31;
    const int wm   = warp >> 1;      // 0..3
    const int wn   = warp & 1;       // 0..1

    // producer mapping
    // A: row = tid>>1 (0..127), half = tid&1 (16 bf16 = 32 B, two 16B chunks)
    const int parow = tid >> 1;
    const int pah   = tid & 1;
    const uint32_t psa = (uint32_t)parow * 80u + (uint32_t)pah * 32u;
    const __nv_bfloat16* pAh = Ah + (size_t)(row0 + parow) * lda + pah * 16;
    const __nv_bfloat16* pAl = Al + (size_t)(row0 + parow) * lda + pah * 16;
    // B: row = tid>>2 (0..63), chunk = tid&3 (8 bf16 = 16 B)
    const int pbrow = tid >> 2;
    const int pbq   = tid & 3;
    const uint32_t psb = (uint32_t)pbrow * 80u + (uint32_t)pbq * 16u;
    const __nv_bfloat16* pBh = Bh + (size_t)(col0 + pbrow) * ldb + pbq * 8;
    const __nv_bfloat16* pBl = Bl + (size_t)(col0 + pbrow) * ldb + pbq * 8;

    // prologue: stage 0 = chunk 0 (group #0)
    {
        const uint32_t st = base;
        CP16(st + psa,                            pAh);
        CP16(st + psa + 16,                       pAh + 8);
        CP16(st + ATILE_B + psa,                  pAl);
        CP16(st + ATILE_B + psa + 16,             pAl + 8);
        CP16(st + 2u * ATILE_B + psb,             pBh);
        CP16(st + 2u * ATILE_B + BTILE_B + psb,   pBl);
        CP_COMMIT();
    }

    float acc[2][2][4];
#pragma unroll
    for (int mt = 0; mt < 2; mt++)
#pragma unroll
        for (int nt = 0; nt < 2; nt++)
#pragma unroll
            for (int r = 0; r < 4; r++) acc[mt][nt][r] = 0.f;
    float acc2[2][2][4];
#pragma unroll
    for (int mt = 0; mt < 2; mt++)
#pragma unroll
        for (int nt = 0; nt < 2; nt++)
#pragma unroll
            for (int r = 0; r < 4; r++) acc2[mt][nt][r] = 0.f;

    const uint32_t aRow  = (uint32_t)(wm * 32 + (lane & 15));
    const uint32_t aSlot = (uint32_t)(lane >> 4);
    const uint32_t bRow  = (uint32_t)(wn * 32 + (lane & 7) + ((lane >> 4) << 3));
    const uint32_t bSlot = (uint32_t)((lane >> 3) & 1);

    for (int i = 0; i < nCh; i++) {
        // 1. everyone done computing on stage (i+1)&1 (chunk i-1) -> refill it
        __syncthreads();
        if (i + 1 < nCh) {
            const int kO = (i + 1) * KC;
            const uint32_t st = base + (uint32_t)((i + 1) & 1) * STAGE_B;
            CP16(st + psa,                          pAh + kO);
            CP16(st + psa + 16,                     pAh + kO + 8);
            CP16(st + ATILE_B + psa,                pAl + kO);
            CP16(st + ATILE_B + psa + 16,           pAl + kO + 8);
            CP16(st + 2u * ATILE_B + psb,           pBh + kO);
            CP16(st + 2u * ATILE_B + BTILE_B + psb, pBl + kO);
        }
        CP_COMMIT();
        // 2. with the refill group now committed, wait_group 1 drains chunk i
        CP_WAIT1();
        __syncthreads();            // chunk i visible to all warps

        const uint32_t buf = base + (uint32_t)(i & 1) * STAGE_B;
#pragma unroll
        for (int s = 0; s < 2; s++) {
            // phase 1: Ah x Bh
            uint32_t a0[2][4];
            uint32_t b0[2][4];      // [g] holds two n-subtiles packed
#pragma unroll
            for (int mt = 0; mt < 2; mt++)
                ldm4(a0[mt], buf + (aRow + (uint32_t)(mt * 16)) * 80u
                                 + (2u * s + aSlot) * 16u);
#pragma unroll
            for (int g = 0; g < 2; g++)
                ldm4(b0[g], buf + 2u * ATILE_B
                                + (bRow + (uint32_t)(g * 16)) * 80u
                                + (2u * s + bSlot) * 16u);
#pragma unroll
            for (int mt = 0; mt < 2; mt++)
#pragma unroll
                for (int g = 0; g < 2; g++) {
                    mma16816(acc [mt][g], a0[mt], b0[g]);
                    mma16816(acc2[mt][g], a0[mt], b0[g] + 2);
                }
            // phase 2: Al x Bh (t dies after)
            {
                uint32_t t[2][4];
#pragma unroll
                for (int mt = 0; mt < 2; mt++)
                    ldm4(t[mt], buf + ATILE_B
                                    + (aRow + (uint32_t)(mt * 16)) * 80u
                                    + (2u * s + aSlot) * 16u);
#pragma unroll
                for (int mt = 0; mt < 2; mt++)
#pragma unroll
                    for (int g = 0; g < 2; g++) {
                        mma16816(acc [mt][g], t[mt], b0[g]);
                        mma16816(acc2[mt][g], t[mt], b0[g] + 2);
                    }
            }
            // phase 3: Ah x Bl (reuse b0 slots)
#pragma unroll
            for (int g = 0; g < 2; g++)
                ldm4(b0[g], buf + 2u * ATILE_B + BTILE_B
                                + (bRow + (uint32_t)(g * 16)) * 80u
                                + (2u * s + bSlot) * 16u);
#pragma unroll
            for (int mt = 0; mt < 2; mt++)
#pragma unroll
                for (int g = 0; g < 2; g++) {
                    mma16816(acc [mt][g], a0[mt], b0[g]);
                    mma16816(acc2[mt][g], a0[mt], b0[g] + 2);
                }
        }
    }

    // epilogue: group g covers n-subtiles {2g (acc), 2g+1 (acc2)}
#pragma unroll
    for (int mt = 0; mt < 2; mt++) {
        const int rbase = row0 + wm * 32 + mt * 16 + (lane >> 2);
#pragma unroll
        for (int g = 0; g < 2; g++) {
#pragma unroll
            for (int half = 0; half < 2; half++) {
                const float* a4 = half ? acc2[mt][g] : acc[mt][g];
                const int nt = 2 * g + half;
                const int cbase = col0 + wn * 32 + nt * 8 + (lane & 3) * 2;
                float v00 = alpha * a4[0];
                float v01 = alpha * a4[1];
                float v10 = alpha * a4[2];
                float v11 = alpha * a4[3];
                if (flags & 4) {
                    uint32_t h0 = pk2(v00, v01);
                    uint32_t l0 = pk2(v00 - __uint_as_float(h0 << 16),
                                      v01 - __uint_as_float(h0 & 0xffff0000u));
                    uint32_t h1 = pk2(v10, v11);
                    uint32_t l1 = pk2(v10 - __uint_as_float(h1 << 16),
                                      v11 - __uint_as_float(h1 & 0xffff0000u));
                    *(uint32_t*)(Ch + zc + (size_t)rbase * ldc + cbase)       = h0;
                    *(uint32_t*)(Cl + zc + (size_t)rbase * ldc + cbase)       = l0;
                    *(uint32_t*)(Ch + zc + (size_t)(rbase + 8) * ldc + cbase) = h1;
                    *(uint32_t*)(Cl + zc + (size_t)(rbase + 8) * ldc + cbase) = l1;
                } else {
                    float2 v0; v0.x = v00; v0.y = v01;
                    float2 v1; v1.x = v10; v1.y = v11;
                    *(float2*)(Cf + zc + (size_t)rbase * ldc + cbase)       = v0;
                    *(float2*)(Cf + zc + (size_t)(rbase + 8) * ldc + cbase) = v1;
                }
            }
        }
    }
}

// ---------------------------------------------------------------------------
// Causal softmax in place; also emits bf16 hi/lo split of P for the PV GEMM.
// One block per (row, head). Cols > row set to exact 0.
// ---------------------------------------------------------------------------
__global__ __launch_bounds__(256) void softmax_causal(
    float* __restrict__ attn,
    __nv_bfloat16* __restrict__ Ph, __nv_bfloat16* __restrict__ Pl)
{
    const int r = blockIdx.x;
    const int h = blockIdx.y;
    const size_t ro = ((size_t)h * S_LEN + r) * S_LEN;
    float* row = attn + ro;
    const int nv  = r + 1;
    const int tid = threadIdx.x;

    float v[8];
    float mx = -1e30f;
#pragma unroll
    for (int i = 0; i < 8; i++) {
        int c = tid + i * 256;
        v[i] = (c < nv) ? row[c] : -1e30f;
        mx = fmaxf(mx, v[i]);
    }

    __shared__ float red[256];
    red[tid] = mx;
    __syncthreads();
#pragma unroll
    for (int s2 = 128; s2 > 0; s2 >>= 1) {
        if (tid < s2) red[tid] = fmaxf(red[tid], red[tid + s2]);
        __syncthreads();
    }
    mx = red[0];
    __syncthreads();

    float sum = 0.f;
#pragma unroll
    for (int i = 0; i < 8; i++) {
        int c = tid + i * 256;
        v[i] = (c < nv) ? expf(v[i] - mx) : 0.f;
        sum += v[i];
    }
    red[tid] = sum;
    __syncthreads();
#pragma unroll
    for (int s2 = 128; s2 > 0; s2 >>= 1) {
        if (tid < s2) red[tid] += red[tid + s2];
        __syncthreads();
    }
    const float inv = 1.f / red[0];

#pragma unroll
    for (int i = 0; i < 8; i++) {
        int c = tid + i * 256;
        float val = v[i] * inv;
        row[c] = val;
        __nv_bfloat16 hb = __float2bfloat16(val);
        Ph[ro + c] = hb;
        Pl[ro + c] = __float2bfloat16(val - __bfloat162float(hb));
    }
}

// ---------------------------------------------------------------------------
// Launch
// Inputs: hidden_states, cos, sin, attention_mask, w_qkv, w_o
// Output: [out (1,2048,3072)] ++ [attn_weights (1,24,2048,2048)]
// ---------------------------------------------------------------------------
extern "C" void kernel_launch(void* const* d_in, const int* in_sizes, int n_in,
                              void* d_out, int out_size)
{
    const float* hidden = (const float*)d_in[0];
    const float* cosb   = (const float*)d_in[1];
    const float* sinb   = (const float*)d_in[2];
    const float* wqkv   = (const float*)d_in[4];
    const float* wo     = (const float*)d_in[5];

    float* out  = (float*)d_out;
    float* attn = out + (size_t)S_LEN * HID;

    float* qkv;
    __nv_bfloat16 *hidh, *hidl, *wqkvh, *wqkvl, *woh, *wol;
    __nv_bfloat16 *qkh, *qkl, *vTh, *vTl, *Ph, *Pl, *aoh, *aol;
    cudaGetSymbolAddress((void**)&qkv,   g_qkv);
    cudaGetSymbolAddress((void**)&hidh,  g_hidh);
    cudaGetSymbolAddress((void**)&hidl,  g_hidl);
    cudaGetSymbolAddress((void**)&wqkvh, g_wqkvh);
    cudaGetSymbolAddress((void**)&wqkvl, g_wqkvl);
    cudaGetSymbolAddress((void**)&woh,   g_woh);
    cudaGetSymbolAddress((void**)&wol,   g_wol);
    cudaGetSymbolAddress((void**)&qkh,   g_qkh);
    cudaGetSymbolAddress((void**)&qkl,   g_qkl);
    cudaGetSymbolAddress((void**)&vTh,   g_vTh);
    cudaGetSymbolAddress((void**)&vTl,   g_vTl);
    cudaGetSymbolAddress((void**)&Ph,    g_Ph);
    cudaGetSymbolAddress((void**)&Pl,    g_Pl);
    cudaGetSymbolAddress((void**)&aoh,   g_aoh);
    cudaGetSymbolAddress((void**)&aol,   g_aol);

    cudaFuncSetAttribute(gemm_bf16, cudaFuncAttributeMaxDynamicSharedMemorySize,
                         GEMM_SMEM);

    // 0. operand splits
    conv_split<<<(S_LEN * HID / 4 + 255) / 256, 256>>>(hidden, hidh, hidl,
                                                       S_LEN * HID / 4);
    conv_split<<<(OPSZ * HID / 4 + 255) / 256, 256>>>(wqkv, wqkvh, wqkvl,
                                                      OPSZ * HID / 4);
    conv_split<<<(HID * HID / 4 + 255) / 256, 256>>>(wo, woh, wol,
                                                     HID * HID / 4);

    // 1. qkv = hidden @ w_qkv^T   (2048 x 5120, K=3072), fp32 out
    gemm_bf16<<<dim3(OPSZ / 64, S_LEN / 128, 1), 256, GEMM_SMEM>>>(
        hidh, hidl, HID, 0, wqkvh, wqkvl, HID, 0, 1,
        qkv, nullptr, nullptr, OPSZ, 0, HID, 1.0f, 0);

    // 2. RoPE + split Q/K;  3. transpose + split V
    rope_split<<<S_LEN * 1024 / 256, 256>>>(qkv, cosb, sinb, qkh, qkl);
    vsplit_T<<<dim3((NKV * HD) / 32, S_LEN / 32), dim3(32, 8)>>>(qkv, vTh, vTl);

    // 4. scores = Q K^T * scale (causal tiles only) -> attn fp32
    gemm_bf16<<<dim3(S_LEN / 64, S_LEN / 128, NH), 256, GEMM_SMEM>>>(
        qkh, qkl, QK_COLS, HD,
        qkh + HID, qkl + HID, QK_COLS, HD, 3,
        attn, nullptr, nullptr, S_LEN, (long long)S_LEN * S_LEN,
        HD, SCALING, 1);

    // 5. softmax in place + P hi/lo emit
    softmax_causal<<<dim3(S_LEN, NH), 256>>>(attn, Ph, Pl);

    // 6. ao(hi/lo) = P @ V   (K limited to row0+128)
    gemm_bf16<<<dim3(HD / 64, S_LEN / 128, NH), 256, GEMM_SMEM>>>(
        Ph, Pl, S_LEN, (long long)S_LEN * S_LEN,
        vTh, vTl, S_LEN, (long long)HD * S_LEN, 3,
        nullptr, aoh, aol, HID, HD,
        S_LEN, 1.0f, 2 | 4);

    // 7. out = ao @ w_o^T   (2048 x 3072, K=3072), fp32 out
    gemm_bf16<<<dim3(HID / 64, S_LEN / 128, 1), 256, GEMM_SMEM>>>(
        aoh, aol, HID, 0, woh, wol, HID, 0, 1,
        out, nullptr, nullptr, HID, 0, HID, 1.0f, 0);
}

// round 9
// speedup vs baseline: 1.0362x; 1.0362x over previous
#include <cuda_runtime.h>
#include <cuda_bf16.h>
#include <cstdint>

#define S_LEN 2048
#define HID 3072
#define NH 24
#define NKV 8
#define HD 128
#define OPSZ 5120
#define QK_COLS 4096
#define SCALING 0.08838834764831845f

// ---------------------------------------------------------------------------
// Scratch (__device__ globals; runtime allocation forbidden)
// ---------------------------------------------------------------------------
__device__ float g_qkv[(size_t)S_LEN * OPSZ];                                  // 42 MB
__device__ __nv_bfloat16 g_hidh [(size_t)S_LEN * HID],  g_hidl [(size_t)S_LEN * HID];
__device__ __nv_bfloat16 g_wqkvh[(size_t)OPSZ * HID],   g_wqkvl[(size_t)OPSZ * HID];
__device__ __nv_bfloat16 g_woh  [(size_t)HID * HID],    g_wol  [(size_t)HID * HID];
__device__ __nv_bfloat16 g_qkh  [(size_t)S_LEN * QK_COLS], g_qkl[(size_t)S_LEN * QK_COLS];
__device__ __nv_bfloat16 g_vTh  [(size_t)NKV * HD * S_LEN], g_vTl[(size_t)NKV * HD * S_LEN];
__device__ __nv_bfloat16 g_Ph   [(size_t)NH * S_LEN * S_LEN];                  // 201 MB
__device__ __nv_bfloat16 g_Pl   [(size_t)NH * S_LEN * S_LEN];                  // 201 MB
__device__ __nv_bfloat16 g_aoh  [(size_t)S_LEN * HID],  g_aol [(size_t)S_LEN * HID];

// ---------------------------------------------------------------------------
// helpers
// ---------------------------------------------------------------------------
__device__ __forceinline__ uint32_t smem_u32(const void* p) {
    uint32_t a;
    asm("{ .reg .u64 t; cvta.to.shared.u64 t, %1; cvt.u32.u64 %0, t; }"
        : "=r"(a) : "l"(p));
    return a;
}
__device__ __forceinline__ void ldm4(uint32_t* r, uint32_t addr) {
    asm volatile("ldmatrix.sync.aligned.m8n8.x4.shared.b16 {%0,%1,%2,%3}, [%4];"
        : "=r"(r[0]), "=r"(r[1]), "=r"(r[2]), "=r"(r[3]) : "r"(addr));
}
__device__ __forceinline__ void mma16816(float* c, const uint32_t* a,
                                         const uint32_t* b) {
    asm volatile(
        "mma.sync.aligned.m16n8k16.row.col.f32.bf16.bf16.f32 "
        "{%0,%1,%2,%3}, {%4,%5,%6,%7}, {%8,%9}, {%0,%1,%2,%3};"
        : "+f"(c[0]), "+f"(c[1]), "+f"(c[2]), "+f"(c[3])
        : "r"(a[0]), "r"(a[1]), "r"(a[2]), "r"(a[3]), "r"(b[0]), "r"(b[1]));
}
// pack two fp32 -> bf16x2 (lo half = a, hi half = b), round-to-nearest
__device__ __forceinline__ uint32_t pk2(float a, float b) {
    uint32_t r;
    asm("cvt.rn.bf16x2.f32 %0, %1, %2;" : "=r"(r) : "f"(b), "f"(a));
    return r;
}
#define CP16(dst, src) \
    asm volatile("cp.async.cg.shared.global [%0], [%1], 16;" \
                 :: "r"(dst), "l"(src) : "memory")
#define CP_COMMIT() asm volatile("cp.async.commit_group;" ::: "memory")
#define CP_WAIT1()  asm volatile("cp.async.wait_group 1;" ::: "memory")

// ---------------------------------------------------------------------------
// fp32 -> (bf16 hi, bf16 lo) elementwise split, 4 elems/thread
// ---------------------------------------------------------------------------
__global__ __launch_bounds__(256) void conv_split(
    const float* __restrict__ src, __nv_bfloat16* __restrict__ h,
    __nv_bfloat16* __restrict__ l, int n4)
{
    int i = blockIdx.x * 256 + threadIdx.x;
    if (i >= n4) return;
    float4 x = ((const float4*)src)[i];
    uint32_t p0 = pk2(x.x, x.y), p1 = pk2(x.z, x.w);
    float l0 = x.x - __uint_as_float(p0 << 16);
    float l1 = x.y - __uint_as_float(p0 & 0xffff0000u);
    float l2 = x.z - __uint_as_float(p1 << 16);
    float l3 = x.w - __uint_as_float(p1 & 0xffff0000u);
    uint2 hh; hh.x = p0; hh.y = p1;
    uint2 ll; ll.x = pk2(l0, l1); ll.y = pk2(l2, l3);
    ((uint2*)h)[i] = hh;
    ((uint2*)l)[i] = ll;
}

// ---------------------------------------------------------------------------
// Fused RoPE + split on Q/K columns (0..4095) of qkv. 4 elems/thread.
// ---------------------------------------------------------------------------
__global__ __launch_bounds__(256) void rope_split(
    const float* __restrict__ qkv, const float* __restrict__ cosb,
    const float* __restrict__ sinb,
    __nv_bfloat16* __restrict__ qh, __nv_bfloat16* __restrict__ ql)
{
    int idx = blockIdx.x * 256 + threadIdx.x;   // S_LEN * 1024
    int s = idx >> 10;
    int c = (idx & 1023) * 4;
    int d = c & 127;
    const float* row = qkv + (size_t)s * OPSZ;
    float4 x = *(const float4*)(row + c);
    if (d < 96) {
        float4 cc = *(const float4*)(cosb + s * 96 + d);
        float4 ss = *(const float4*)(sinb + s * 96 + d);
        if (d < 48) {
            float4 p = *(const float4*)(row + c + 48);
            x.x = x.x * cc.x - p.x * ss.x;
            x.y = x.y * cc.y - p.y * ss.y;
            x.z = x.z * cc.z - p.z * ss.z;
            x.w = x.w * cc.w - p.w * ss.w;
        } else {
            float4 p = *(const float4*)(row + c - 48);
            x.x = x.x * cc.x + p.x * ss.x;
            x.y = x.y * cc.y + p.y * ss.y;
            x.z = x.z * cc.z + p.z * ss.z;
            x.w = x.w * cc.w + p.w * ss.w;
        }
    }
    uint32_t p0 = pk2(x.x, x.y), p1 = pk2(x.z, x.w);
    float l0 = x.x - __uint_as_float(p0 << 16);
    float l1 = x.y - __uint_as_float(p0 & 0xffff0000u);
    float l2 = x.z - __uint_as_float(p1 << 16);
    float l3 = x.w - __uint_as_float(p1 & 0xffff0000u);
    uint2 hh; hh.x = p0; hh.y = p1;
    uint2 ll; ll.x = pk2(l0, l1); ll.y = pk2(l2, l3);
    size_t o = ((size_t)s * QK_COLS + c) >> 2;
    ((uint2*)qh)[o] = hh;
    ((uint2*)ql)[o] = ll;
}

// ---------------------------------------------------------------------------
// V transpose + split: vT[kv*HD+d][s] = qkv[s][4096+kv*HD+d], SMEM-tiled.
// ---------------------------------------------------------------------------
__global__ __launch_bounds__(256) void vsplit_T(
    const float* __restrict__ qkv,
    __nv_bfloat16* __restrict__ vh, __nv_bfloat16* __restrict__ vl)
{
    __shared__ float tile[32][33];
    const int t0 = blockIdx.x * 32;
    const int s0 = blockIdx.y * 32;
    const int tx = threadIdx.x, ty = threadIdx.y;   // (32, 8)
#pragma unroll
    for (int j = 0; j < 4; j++)
        tile[ty + 8 * j][tx] =
            qkv[(size_t)(s0 + ty + 8 * j) * OPSZ + 4096 + t0 + tx];
    __syncthreads();
#pragma unroll
    for (int j = 0; j < 4; j++) {
        float v = tile[tx][ty + 8 * j];
        __nv_bfloat16 hb = __float2bfloat16(v);
        size_t o = (size_t)(t0 + ty + 8 * j) * S_LEN + s0 + tx;
        vh[o] = hb;
        vl[o] = __float2bfloat16(v - __bfloat162float(hb));
    }
}

// ---------------------------------------------------------------------------
// Generic NT GEMM, bf16 hi/lo operands, compensated (3 HMMA per k16).
// C[M,N] = alpha * (Ah+Al)[M,K] * (Bh+Bl)[N,K]^T  (dropping AlBl term)
// 128x128 CTA tile, 256 threads (8 warps, warp tile 64x32), KC=32,
// 2-stage cp.async double buffer, 80B SMEM row pitch, 2 CTAs/SM.
// Fragment schedule per k16: (Ah,Bh)->MMA, Bl->MMA, Ah<-Al->MMA
//   => 12 LDSM / 48 MMA per s-step (ratio 4).
// flags: 1 = causal tile skip, 2 = K limited to row0+128, 4 = split output.
// ---------------------------------------------------------------------------
#define KC 32
#define TILE80 10240u              // 128 rows * 80 B
#define STAGE_B (4u * TILE80)      // Ah Al Bh Bl = 40960
#define NSTAGE  2
#define GEMM_SMEM (NSTAGE * STAGE_B)            // 81920

__global__ __launch_bounds__(256, 2) void gemm_bf16(
    const __nv_bfloat16* __restrict__ Ah, const __nv_bfloat16* __restrict__ Al,
    int lda, long long sAz,
    const __nv_bfloat16* __restrict__ Bh, const __nv_bfloat16* __restrict__ Bl,
    int ldb, long long sBz, int kvdiv,
    float* __restrict__ Cf, __nv_bfloat16* __restrict__ Ch,
    __nv_bfloat16* __restrict__ Cl, int ldc, long long sCz,
    int K, float alpha, int flags)
{
    const int row0 = blockIdx.y << 7;
    const int col0 = blockIdx.x << 7;
    if ((flags & 1) && col0 > row0) return;
    const int z = blockIdx.z;
    const size_t za = (size_t)z * sAz;
    const size_t zb = (size_t)(z / kvdiv) * sBz;
    const size_t zc = (size_t)z * sCz;
    Ah += za; Al += za; Bh += zb; Bl += zb;
    const int Keff = (flags & 2) ? ((K < row0 + 128) ? K : row0 + 128) : K;
    const int nCh  = Keff >> 5;

    extern __shared__ char smem[];
    const uint32_t base = smem_u32(smem);

    const int tid  = threadIdx.x;
    const int warp = tid >> 5;
    const int lane = tid & 31;
    const int wm   = warp >> 2;      // 0..1  (64-row slab)
    const int wn   = warp & 3;       // 0..3  (32-col slab)

    // producer mapping (same for all four 128x80B tiles):
    // row = tid>>1 (0..127), half = tid&1 -> 32 B (two CP16)
    const int prow = tid >> 1;
    const int phf  = tid & 1;
    const uint32_t pst = (uint32_t)prow * 80u + (uint32_t)phf * 32u;
    const __nv_bfloat16* pAh = Ah + (size_t)(row0 + prow) * lda + phf * 16;
    const __nv_bfloat16* pAl = Al + (size_t)(row0 + prow) * lda + phf * 16;
    const __nv_bfloat16* pBh = Bh + (size_t)(col0 + prow) * ldb + phf * 16;
    const __nv_bfloat16* pBl = Bl + (size_t)(col0 + prow) * ldb + phf * 16;

    // prologue: stage 0 = chunk 0 (group #0)
    {
        const uint32_t st = base;
        CP16(st + pst,                 pAh);
        CP16(st + pst + 16,            pAh + 8);
        CP16(st + TILE80 + pst,        pAl);
        CP16(st + TILE80 + pst + 16,   pAl + 8);
        CP16(st + 2u*TILE80 + pst,     pBh);
        CP16(st + 2u*TILE80 + pst + 16,pBh + 8);
        CP16(st + 3u*TILE80 + pst,     pBl);
        CP16(st + 3u*TILE80 + pst + 16,pBl + 8);
        CP_COMMIT();
    }

    // acc[mt][g]  = n-subtile 2g,  acc2[mt][g] = n-subtile 2g+1
    float acc [4][2][4];
    float acc2[4][2][4];
#pragma unroll
    for (int mt = 0; mt < 4; mt++)
#pragma unroll
        for (int g = 0; g < 2; g++)
#pragma unroll
            for (int r = 0; r < 4; r++) { acc[mt][g][r] = 0.f; acc2[mt][g][r] = 0.f; }

    const uint32_t aRow  = (uint32_t)(wm * 64 + (lane & 15));
    const uint32_t aSlot = (uint32_t)(lane >> 4);
    const uint32_t bRow  = (uint32_t)(wn * 32 + (lane & 7) + ((lane >> 4) << 3));
    const uint32_t bSlot = (uint32_t)((lane >> 3) & 1);

    for (int i = 0; i < nCh; i++) {
        // 1. everyone done computing on the other stage -> refill it
        __syncthreads();
        if (i + 1 < nCh) {
            const int kO = (i + 1) * KC;
            const uint32_t st = base + (uint32_t)((i + 1) & 1) * STAGE_B;
            CP16(st + pst,                 pAh + kO);
            CP16(st + pst + 16,            pAh + kO + 8);
            CP16(st + TILE80 + pst,        pAl + kO);
            CP16(st + TILE80 + pst + 16,   pAl + kO + 8);
            CP16(st + 2u*TILE80 + pst,     pBh + kO);
            CP16(st + 2u*TILE80 + pst + 16,pBh + kO + 8);
            CP16(st + 3u*TILE80 + pst,     pBl + kO);
            CP16(st + 3u*TILE80 + pst + 16,pBl + kO + 8);
        }
        CP_COMMIT();
        // 2. refill group committed -> wait_group 1 drains chunk i
        CP_WAIT1();
        __syncthreads();            // chunk i visible to all warps

        const uint32_t buf = base + (uint32_t)(i & 1) * STAGE_B;
#pragma unroll
        for (int s = 0; s < 2; s++) {
            uint32_t a[4][4];       // Ah, later overwritten by Al
            uint32_t bh[2][4];      // Bh (two n-groups, 2 subtiles each)
            uint32_t bl[2][4];      // Bl
            // phase 1: Ah x Bh
#pragma unroll
            for (int mt = 0; mt < 4; mt++)
                ldm4(a[mt], buf + (aRow + (uint32_t)(mt * 16)) * 80u
                                + (2u * s + aSlot) * 16u);
#pragma unroll
            for (int g = 0; g < 2; g++)
                ldm4(bh[g], buf + 2u*TILE80
                                + (bRow + (uint32_t)(g * 16)) * 80u
                                + (2u * s + bSlot) * 16u);
#pragma unroll
            for (int mt = 0; mt < 4; mt++)
#pragma unroll
                for (int g = 0; g < 2; g++) {
                    mma16816(acc [mt][g], a[mt], bh[g]);
                    mma16816(acc2[mt][g], a[mt], bh[g] + 2);
                }
            // phase 2: Ah x Bl
#pragma unroll
            for (int g = 0; g < 2; g++)
                ldm4(bl[g], buf + 3u*TILE80
                                + (bRow + (uint32_t)(g * 16)) * 80u
                                + (2u * s + bSlot) * 16u);
#pragma unroll
            for (int mt = 0; mt < 4; mt++)
#pragma unroll
                for (int g = 0; g < 2; g++) {
                    mma16816(acc [mt][g], a[mt], bl[g]);
                    mma16816(acc2[mt][g], a[mt], bl[g] + 2);
                }
            // phase 3: Al x Bh (overwrite a)
#pragma unroll
            for (int mt = 0; mt < 4; mt++)
                ldm4(a[mt], buf + TILE80
                                + (aRow + (uint32_t)(mt * 16)) * 80u
                                + (2u * s + aSlot) * 16u);
#pragma unroll
            for (int mt = 0; mt < 4; mt++)
#pragma unroll
                for (int g = 0; g < 2; g++) {
                    mma16816(acc [mt][g], a[mt], bh[g]);
                    mma16816(acc2[mt][g], a[mt], bh[g] + 2);
                }
        }
    }

    // epilogue: group g covers n-subtiles {2g (acc), 2g+1 (acc2)}
#pragma unroll
    for (int mt = 0; mt < 4; mt++) {
        const int rbase = row0 + wm * 64 + mt * 16 + (lane >> 2);
#pragma unroll
        for (int g = 0; g < 2; g++) {
#pragma unroll
            for (int half = 0; half < 2; half++) {
                const float* a4 = half ? acc2[mt][g] : acc[mt][g];
                const int nt = 2 * g + half;
                const int cbase = col0 + wn * 32 + nt * 8 + (lane & 3) * 2;
                float v00 = alpha * a4[0];
                float v01 = alpha * a4[1];
                float v10 = alpha * a4[2];
                float v11 = alpha * a4[3];
                if (flags & 4) {
                    uint32_t h0 = pk2(v00, v01);
                    uint32_t l0 = pk2(v00 - __uint_as_float(h0 << 16),
                                      v01 - __uint_as_float(h0 & 0xffff0000u));
                    uint32_t h1 = pk2(v10, v11);
                    uint32_t l1 = pk2(v10 - __uint_as_float(h1 << 16),
                                      v11 - __uint_as_float(h1 & 0xffff0000u));
                    *(uint32_t*)(Ch + zc + (size_t)rbase * ldc + cbase)       = h0;
                    *(uint32_t*)(Cl + zc + (size_t)rbase * ldc + cbase)       = l0;
                    *(uint32_t*)(Ch + zc + (size_t)(rbase + 8) * ldc + cbase) = h1;
                    *(uint32_t*)(Cl + zc + (size_t)(rbase + 8) * ldc + cbase) = l1;
                } else {
                    float2 v0; v0.x = v00; v0.y = v01;
                    float2 v1; v1.x = v10; v1.y = v11;
                    *(float2*)(Cf + zc + (size_t)rbase * ldc + cbase)       = v0;
                    *(float2*)(Cf + zc + (size_t)(rbase + 8) * ldc + cbase) = v1;
                }
            }
        }
    }
}

// ---------------------------------------------------------------------------
// Causal softmax in place; also emits bf16 hi/lo split of P for the PV GEMM.
// One block per (row, head). Cols > row set to exact 0.
// ---------------------------------------------------------------------------
__global__ __launch_bounds__(256) void softmax_causal(
    float* __restrict__ attn,
    __nv_bfloat16* __restrict__ Ph, __nv_bfloat16* __restrict__ Pl)
{
    const int r = blockIdx.x;
    const int h = blockIdx.y;
    const size_t ro = ((size_t)h * S_LEN + r) * S_LEN;
    float* row = attn + ro;
    const int nv  = r + 1;
    const int tid = threadIdx.x;

    float v[8];
    float mx = -1e30f;
#pragma unroll
    for (int i = 0; i < 8; i++) {
        int c = tid + i * 256;
        v[i] = (c < nv) ? row[c] : -1e30f;
        mx = fmaxf(mx, v[i]);
    }

    __shared__ float red[256];
    red[tid] = mx;
    __syncthreads();
#pragma unroll
    for (int s2 = 128; s2 > 0; s2 >>= 1) {
        if (tid < s2) red[tid] = fmaxf(red[tid], red[tid + s2]);
        __syncthreads();
    }
    mx = red[0];
    __syncthreads();

    float sum = 0.f;
#pragma unroll
    for (int i = 0; i < 8; i++) {
        int c = tid + i * 256;
        v[i] = (c < nv) ? expf(v[i] - mx) : 0.f;
        sum += v[i];
    }
    red[tid] = sum;
    __syncthreads();
#pragma unroll
    for (int s2 = 128; s2 > 0; s2 >>= 1) {
        if (tid < s2) red[tid] += red[tid + s2];
        __syncthreads();
    }
    const float inv = 1.f / red[0];

#pragma unroll
    for (int i = 0; i < 8; i++) {
        int c = tid + i * 256;
        float val = v[i] * inv;
        row[c] = val;
        __nv_bfloat16 hb = __float2bfloat16(val);
        Ph[ro + c] = hb;
        Pl[ro + c] = __float2bfloat16(val - __bfloat162float(hb));
    }
}

// ---------------------------------------------------------------------------
// Launch
// Inputs: hidden_states, cos, sin, attention_mask, w_qkv, w_o
// Output: [out (1,2048,3072)] ++ [attn_weights (1,24,2048,2048)]
// ---------------------------------------------------------------------------
extern "C" void kernel_launch(void* const* d_in, const int* in_sizes, int n_in,
                              void* d_out, int out_size)
{
    const float* hidden = (const float*)d_in[0];
    const float* cosb   = (const float*)d_in[1];
    const float* sinb   = (const float*)d_in[2];
    const float* wqkv   = (const float*)d_in[4];
    const float* wo     = (const float*)d_in[5];

    float* out  = (float*)d_out;
    float* attn = out + (size_t)S_LEN * HID;

    float* qkv;
    __nv_bfloat16 *hidh, *hidl, *wqkvh, *wqkvl, *woh, *wol;
    __nv_bfloat16 *qkh, *qkl, *vTh, *vTl, *Ph, *Pl, *aoh, *aol;
    cudaGetSymbolAddress((void**)&qkv,   g_qkv);
    cudaGetSymbolAddress((void**)&hidh,  g_hidh);
    cudaGetSymbolAddress((void**)&hidl,  g_hidl);
    cudaGetSymbolAddress((void**)&wqkvh, g_wqkvh);
    cudaGetSymbolAddress((void**)&wqkvl, g_wqkvl);
    cudaGetSymbolAddress((void**)&woh,   g_woh);
    cudaGetSymbolAddress((void**)&wol,   g_wol);
    cudaGetSymbolAddress((void**)&qkh,   g_qkh);
    cudaGetSymbolAddress((void**)&qkl,   g_qkl);
    cudaGetSymbolAddress((void**)&vTh,   g_vTh);
    cudaGetSymbolAddress((void**)&vTl,   g_vTl);
    cudaGetSymbolAddress((void**)&Ph,    g_Ph);
    cudaGetSymbolAddress((void**)&Pl,    g_Pl);
    cudaGetSymbolAddress((void**)&aoh,   g_aoh);
    cudaGetSymbolAddress((void**)&aol,   g_aol);

    cudaFuncSetAttribute(gemm_bf16, cudaFuncAttributeMaxDynamicSharedMemorySize,
                         GEMM_SMEM);

    // 0. operand splits
    conv_split<<<(S_LEN * HID / 4 + 255) / 256, 256>>>(hidden, hidh, hidl,
                                                       S_LEN * HID / 4);
    conv_split<<<(OPSZ * HID / 4 + 255) / 256, 256>>>(wqkv, wqkvh, wqkvl,
                                                      OPSZ * HID / 4);
    conv_split<<<(HID * HID / 4 + 255) / 256, 256>>>(wo, woh, wol,
                                                     HID * HID / 4);

    // 1. qkv = hidden @ w_qkv^T   (2048 x 5120, K=3072), fp32 out
    gemm_bf16<<<dim3(OPSZ / 128, S_LEN / 128, 1), 256, GEMM_SMEM>>>(
        hidh, hidl, HID, 0, wqkvh, wqkvl, HID, 0, 1,
        qkv, nullptr, nullptr, OPSZ, 0, HID, 1.0f, 0);

    // 2. RoPE + split Q/K;  3. transpose + split V
    rope_split<<<S_LEN * 1024 / 256, 256>>>(qkv, cosb, sinb, qkh, qkl);
    vsplit_T<<<dim3((NKV * HD) / 32, S_LEN / 32), dim3(32, 8)>>>(qkv, vTh, vTl);

    // 4. scores = Q K^T * scale (causal tiles only) -> attn fp32
    gemm_bf16<<<dim3(S_LEN / 128, S_LEN / 128, NH), 256, GEMM_SMEM>>>(
        qkh, qkl, QK_COLS, HD,
        qkh + HID, qkl + HID, QK_COLS, HD, 3,
        attn, nullptr, nullptr, S_LEN, (long long)S_LEN * S_LEN,
        HD, SCALING, 1);

    // 5. softmax in place + P hi/lo emit
    softmax_causal<<<dim3(S_LEN, NH), 256>>>(attn, Ph, Pl);

    // 6. ao(hi/lo) = P @ V   (K limited to row0+128)
    gemm_bf16<<<dim3(HD / 128, S_LEN / 128, NH), 256, GEMM_SMEM>>>(
        Ph, Pl, S_LEN, (long long)S_LEN * S_LEN,
        vTh, vTl, S_LEN, (long long)HD * S_LEN, 3,
        nullptr, aoh, aol, HID, HD,
        S_LEN, 1.0f, 2 | 4);

    // 7. out = ao @ w_o^T   (2048 x 3072, K=3072), fp32 out
    gemm_bf16<<<dim3(HID / 128, S_LEN / 128, 1), 256, GEMM_SMEM>>>(
        aoh, aol, HID, 0, woh, wol, HID, 0, 1,
        out, nullptr, nullptr, HID, 0, HID, 1.0f, 0);
}

// round 10
// speedup vs baseline: 1.1192x; 1.0801x over previous
#include <cuda_runtime.h>
#include <cuda_bf16.h>
#include <cstdint>

#define S_LEN 2048
#define HID 3072
#define NH 24
#define NKV 8
#define HD 128
#define OPSZ 5120
#define QK_COLS 4096
#define SCALING 0.08838834764831845f

// ---------------------------------------------------------------------------
// Scratch (__device__ globals; runtime allocation forbidden)
// ---------------------------------------------------------------------------
__device__ float g_qkv[(size_t)S_LEN * OPSZ];                                  // 42 MB
__device__ __nv_bfloat16 g_hidh [(size_t)S_LEN * HID],  g_hidl [(size_t)S_LEN * HID];
__device__ __nv_bfloat16 g_wqkvh[(size_t)OPSZ * HID],   g_wqkvl[(size_t)OPSZ * HID];
__device__ __nv_bfloat16 g_woh  [(size_t)HID * HID],    g_wol  [(size_t)HID * HID];
__device__ __nv_bfloat16 g_qkh  [(size_t)S_LEN * QK_COLS], g_qkl[(size_t)S_LEN * QK_COLS];
__device__ __nv_bfloat16 g_vTh  [(size_t)NKV * HD * S_LEN], g_vTl[(size_t)NKV * HD * S_LEN];
__device__ __nv_bfloat16 g_Ph   [(size_t)NH * S_LEN * S_LEN];                  // 201 MB
__device__ __nv_bfloat16 g_Pl   [(size_t)NH * S_LEN * S_LEN];                  // 201 MB
__device__ __nv_bfloat16 g_aoh  [(size_t)S_LEN * HID],  g_aol [(size_t)S_LEN * HID];

// ---------------------------------------------------------------------------
// helpers
// ---------------------------------------------------------------------------
__device__ __forceinline__ uint32_t smem_u32(const void* p) {
    uint32_t a;
    asm("{ .reg .u64 t; cvta.to.shared.u64 t, %1; cvt.u32.u64 %0, t; }"
        : "=r"(a) : "l"(p));
    return a;
}
__device__ __forceinline__ void ldm4(uint32_t* r, uint32_t addr) {
    asm volatile("ldmatrix.sync.aligned.m8n8.x4.shared.b16 {%0,%1,%2,%3}, [%4];"
        : "=r"(r[0]), "=r"(r[1]), "=r"(r[2]), "=r"(r[3]) : "r"(addr));
}
__device__ __forceinline__ void mma16816(float* c, const uint32_t* a,
                                         const uint32_t* b) {
    asm volatile(
        "mma.sync.aligned.m16n8k16.row.col.f32.bf16.bf16.f32 "
        "{%0,%1,%2,%3}, {%4,%5,%6,%7}, {%8,%9}, {%0,%1,%2,%3};"
        : "+f"(c[0]), "+f"(c[1]), "+f"(c[2]), "+f"(c[3])
        : "r"(a[0]), "r"(a[1]), "r"(a[2]), "r"(a[3]), "r"(b[0]), "r"(b[1]));
}
// pack two fp32 -> bf16x2 (lo half = a, hi half = b), round-to-nearest
__device__ __forceinline__ uint32_t pk2(float a, float b) {
    uint32_t r;
    asm("cvt.rn.bf16x2.f32 %0, %1, %2;" : "=r"(r) : "f"(b), "f"(a));
    return r;
}
#define CP16(dst, src) \
    asm volatile("cp.async.cg.shared.global [%0], [%1], 16;" \
                 :: "r"(dst), "l"(src) : "memory")
#define CP_COMMIT() asm volatile("cp.async.commit_group;" ::: "memory")
#define CP_WAIT2()  asm volatile("cp.async.wait_group 2;" ::: "memory")

// ---------------------------------------------------------------------------
// fp32 -> (bf16 hi, bf16 lo) elementwise split, 4 elems/thread
// ---------------------------------------------------------------------------
__global__ __launch_bounds__(256) void conv_split(
    const float* __restrict__ src, __nv_bfloat16* __restrict__ h,
    __nv_bfloat16* __restrict__ l, int n4)
{
    int i = blockIdx.x * 256 + threadIdx.x;
    if (i >= n4) return;
    float4 x = ((const float4*)src)[i];
    uint32_t p0 = pk2(x.x, x.y), p1 = pk2(x.z, x.w);
    float l0 = x.x - __uint_as_float(p0 << 16);
    float l1 = x.y - __uint_as_float(p0 & 0xffff0000u);
    float l2 = x.z - __uint_as_float(p1 << 16);
    float l3 = x.w - __uint_as_float(p1 & 0xffff0000u);
    uint2 hh; hh.x = p0; hh.y = p1;
    uint2 ll; ll.x = pk2(l0, l1); ll.y = pk2(l2, l3);
    ((uint2*)h)[i] = hh;
    ((uint2*)l)[i] = ll;
}

// ---------------------------------------------------------------------------
// Fused RoPE + split on Q/K columns (0..4095) of qkv. 4 elems/thread.
// ---------------------------------------------------------------------------
__global__ __launch_bounds__(256) void rope_split(
    const float* __restrict__ qkv, const float* __restrict__ cosb,
    const float* __restrict__ sinb,
    __nv_bfloat16* __restrict__ qh, __nv_bfloat16* __restrict__ ql)
{
    int idx = blockIdx.x * 256 + threadIdx.x;   // S_LEN * 1024
    int s = idx >> 10;
    int c = (idx & 1023) * 4;
    int d = c & 127;
    const float* row = qkv + (size_t)s * OPSZ;
    float4 x = *(const float4*)(row + c);
    if (d < 96) {
        float4 cc = *(const float4*)(cosb + s * 96 + d);
        float4 ss = *(const float4*)(sinb + s * 96 + d);
        if (d < 48) {
            float4 p = *(const float4*)(row + c + 48);
            x.x = x.x * cc.x - p.x * ss.x;
            x.y = x.y * cc.y - p.y * ss.y;
            x.z = x.z * cc.z - p.z * ss.z;
            x.w = x.w * cc.w - p.w * ss.w;
        } else {
            float4 p = *(const float4*)(row + c - 48);
            x.x = x.x * cc.x + p.x * ss.x;
            x.y = x.y * cc.y + p.y * ss.y;
            x.z = x.z * cc.z + p.z * ss.z;
            x.w = x.w * cc.w + p.w * ss.w;
        }
    }
    uint32_t p0 = pk2(x.x, x.y), p1 = pk2(x.z, x.w);
    float l0 = x.x - __uint_as_float(p0 << 16);
    float l1 = x.y - __uint_as_float(p0 & 0xffff0000u);
    float l2 = x.z - __uint_as_float(p1 << 16);
    float l3 = x.w - __uint_as_float(p1 & 0xffff0000u);
    uint2 hh; hh.x = p0; hh.y = p1;
    uint2 ll; ll.x = pk2(l0, l1); ll.y = pk2(l2, l3);
    size_t o = ((size_t)s * QK_COLS + c) >> 2;
    ((uint2*)qh)[o] = hh;
    ((uint2*)ql)[o] = ll;
}

// ---------------------------------------------------------------------------
// V transpose + split: vT[kv*HD+d][s] = qkv[s][4096+kv*HD+d], SMEM-tiled.
// ---------------------------------------------------------------------------
__global__ __launch_bounds__(256) void vsplit_T(
    const float* __restrict__ qkv,
    __nv_bfloat16* __restrict__ vh, __nv_bfloat16* __restrict__ vl)
{
    __shared__ float tile[32][33];
    const int t0 = blockIdx.x * 32;
    const int s0 = blockIdx.y * 32;
    const int tx = threadIdx.x, ty = threadIdx.y;   // (32, 8)
#pragma unroll
    for (int j = 0; j < 4; j++)
        tile[ty + 8 * j][tx] =
            qkv[(size_t)(s0 + ty + 8 * j) * OPSZ + 4096 + t0 + tx];
    __syncthreads();
#pragma unroll
    for (int j = 0; j < 4; j++) {
        float v = tile[tx][ty + 8 * j];
        __nv_bfloat16 hb = __float2bfloat16(v);
        size_t o = (size_t)(t0 + ty + 8 * j) * S_LEN + s0 + tx;
        vh[o] = hb;
        vl[o] = __float2bfloat16(v - __bfloat162float(hb));
    }
}

// ---------------------------------------------------------------------------
// Generic NT GEMM, bf16 hi/lo operands, compensated (3 HMMA per k16).
// C[M,N] = alpha * (Ah+Al)[M,K] * (Bh+Bl)[N,K]^T  (dropping AlBl term)
// 128x128 tile, 512 threads (16 warps, warp tile 32x32), KC=32,
// 4-stage cp.async pipeline (R5 proven schedule), phase-grouped MMA order.
// flags: 1 = causal tile skip, 2 = K limited to row0+128, 4 = split output.
// ---------------------------------------------------------------------------
#define KC 32
#define TILE80 10240u              // 128 rows * 80 B
#define STAGE_B (4u * TILE80)      // Ah Al Bh Bl = 40960
#define NSTAGE  4
#define GEMM_SMEM (NSTAGE * STAGE_B)   // 163840

__global__ __launch_bounds__(512) void gemm_bf16(
    const __nv_bfloat16* __restrict__ Ah, const __nv_bfloat16* __restrict__ Al,
    int lda, long long sAz,
    const __nv_bfloat16* __restrict__ Bh, const __nv_bfloat16* __restrict__ Bl,
    int ldb, long long sBz, int kvdiv,
    float* __restrict__ Cf, __nv_bfloat16* __restrict__ Ch,
    __nv_bfloat16* __restrict__ Cl, int ldc, long long sCz,
    int K, float alpha, int flags)
{
    const int row0 = blockIdx.y << 7;
    const int col0 = blockIdx.x << 7;
    if ((flags & 1) && col0 > row0) return;
    const int z = blockIdx.z;
    const size_t za = (size_t)z * sAz;
    const size_t zb = (size_t)(z / kvdiv) * sBz;
    const size_t zc = (size_t)z * sCz;
    Ah += za; Al += za; Bh += zb; Bl += zb;
    const int Keff = (flags & 2) ? ((K < row0 + 128) ? K : row0 + 128) : K;
    const int nCh  = Keff >> 5;

    extern __shared__ char smem[];
    const uint32_t base = smem_u32(smem);

    const int tid  = threadIdx.x;
    const int warp = tid >> 5;
    const int lane = tid & 31;
    const int wm   = warp >> 2;      // 0..3
    const int wn   = warp & 3;       // 0..3

    // producer mapping: row = tid>>2 (0..127), 16B chunk = tid&3
    const int prow = tid >> 2;
    const int pq   = tid & 3;
    const uint32_t pst = (uint32_t)prow * 80u + (uint32_t)pq * 16u;
    const __nv_bfloat16* pAh = Ah + (size_t)(row0 + prow) * lda + pq * 8;
    const __nv_bfloat16* pAl = Al + (size_t)(row0 + prow) * lda + pq * 8;
    const __nv_bfloat16* pBh = Bh + (size_t)(col0 + prow) * ldb + pq * 8;
    const __nv_bfloat16* pBl = Bl + (size_t)(col0 + prow) * ldb + pq * 8;

    // prologue: stages 0..2 (nCh >= 4 for every launch in this problem)
#pragma unroll
    for (int s = 0; s < NSTAGE - 1; s++) {
        const int kO = s * KC;
        const uint32_t st = base + (uint32_t)s * STAGE_B;
        CP16(st + pst,               pAh + kO);
        CP16(st + TILE80 + pst,      pAl + kO);
        CP16(st + 2u * TILE80 + pst, pBh + kO);
        CP16(st + 3u * TILE80 + pst, pBl + kO);
        CP_COMMIT();
    }

    // acc[mt][g] = n-subtile 2g, acc2[mt][g] = n-subtile 2g+1
    float acc [2][2][4];
    float acc2[2][2][4];
#pragma unroll
    for (int mt = 0; mt < 2; mt++)
#pragma unroll
        for (int g = 0; g < 2; g++)
#pragma unroll
            for (int r = 0; r < 4; r++) { acc[mt][g][r] = 0.f; acc2[mt][g][r] = 0.f; }

    const uint32_t aRow  = (uint32_t)(wm * 32 + (lane & 15));
    const uint32_t aSlot = (uint32_t)(lane >> 4);
    const uint32_t bRow  = (uint32_t)(wn * 32 + (lane & 7) + ((lane >> 4) << 3));
    const uint32_t bSlot = (uint32_t)((lane >> 3) & 1);

    for (int i = 0; i < nCh; i++) {
        CP_WAIT2();                 // chunk i landed
        __syncthreads();            // all warps done with the stage being refilled
        if (i + NSTAGE - 1 < nCh) {
            const int kO = (i + NSTAGE - 1) * KC;
            const uint32_t st =
                base + (uint32_t)((i + NSTAGE - 1) & (NSTAGE - 1)) * STAGE_B;
            CP16(st + pst,               pAh + kO);
            CP16(st + TILE80 + pst,      pAl + kO);
            CP16(st + 2u * TILE80 + pst, pBh + kO);
            CP16(st + 3u * TILE80 + pst, pBl + kO);
        }
        CP_COMMIT();

        const uint32_t buf = base + (uint32_t)(i & (NSTAGE - 1)) * STAGE_B;
#pragma unroll
        for (int s = 0; s < 2; s++) {
            uint32_t a[2][4];       // Ah, later overwritten by Al
            uint32_t bh2[2][4];     // Bh (two subtiles per group)
            uint32_t bl2[2][4];     // Bl
            // phase 1: Ah x Bh
#pragma unroll
            for (int mt = 0; mt < 2; mt++)
                ldm4(a[mt], buf + (aRow + (uint32_t)(mt * 16)) * 80u
                                + (2u * s + aSlot) * 16u);
#pragma unroll
            for (int g = 0; g < 2; g++)
                ldm4(bh2[g], buf + 2u * TILE80
                                 + (bRow + (uint32_t)(g * 16)) * 80u
                                 + (2u * s + bSlot) * 16u);
#pragma unroll
            for (int mt = 0; mt < 2; mt++)
#pragma unroll
                for (int g = 0; g < 2; g++) {
                    mma16816(acc [mt][g], a[mt], bh2[g]);
                    mma16816(acc2[mt][g], a[mt], bh2[g] + 2);
                }
            // phase 2: Ah x Bl
#pragma unroll
            for (int g = 0; g < 2; g++)
                ldm4(bl2[g], buf + 3u * TILE80
                                 + (bRow + (uint32_t)(g * 16)) * 80u
                                 + (2u * s + bSlot) * 16u);
#pragma unroll
            for (int mt = 0; mt < 2; mt++)
#pragma unroll
                for (int g = 0; g < 2; g++) {
                    mma16816(acc [mt][g], a[mt], bl2[g]);
                    mma16816(acc2[mt][g], a[mt], bl2[g] + 2);
                }
            // phase 3: Al x Bh (overwrite a)
#pragma unroll
            for (int mt = 0; mt < 2; mt++)
                ldm4(a[mt], buf + TILE80
                                + (aRow + (uint32_t)(mt * 16)) * 80u
                                + (2u * s + aSlot) * 16u);
#pragma unroll
            for (int mt = 0; mt < 2; mt++)
#pragma unroll
                for (int g = 0; g < 2; g++) {
                    mma16816(acc [mt][g], a[mt], bh2[g]);
                    mma16816(acc2[mt][g], a[mt], bh2[g] + 2);
                }
        }
    }

    // epilogue: group g covers n-subtiles {2g (acc), 2g+1 (acc2)}
#pragma unroll
    for (int mt = 0; mt < 2; mt++) {
        const int rbase = row0 + wm * 32 + mt * 16 + (lane >> 2);
#pragma unroll
        for (int g = 0; g < 2; g++) {
#pragma unroll
            for (int half = 0; half < 2; half++) {
                const float* a4 = half ? acc2[mt][g] : acc[mt][g];
                const int nt = 2 * g + half;
                const int cbase = col0 + wn * 32 + nt * 8 + (lane & 3) * 2;
                float v00 = alpha * a4[0];
                float v01 = alpha * a4[1];
                float v10 = alpha * a4[2];
                float v11 = alpha * a4[3];
                if (flags & 4) {
                    uint32_t h0 = pk2(v00, v01);
                    uint32_t l0 = pk2(v00 - __uint_as_float(h0 << 16),
                                      v01 - __uint_as_float(h0 & 0xffff0000u));
                    uint32_t h1 = pk2(v10, v11);
                    uint32_t l1 = pk2(v10 - __uint_as_float(h1 << 16),
                                      v11 - __uint_as_float(h1 & 0xffff0000u));
                    *(uint32_t*)(Ch + zc + (size_t)rbase * ldc + cbase)       = h0;
                    *(uint32_t*)(Cl + zc + (size_t)rbase * ldc + cbase)       = l0;
                    *(uint32_t*)(Ch + zc + (size_t)(rbase + 8) * ldc + cbase) = h1;
                    *(uint32_t*)(Cl + zc + (size_t)(rbase + 8) * ldc + cbase) = l1;
                } else {
                    float2 v0; v0.x = v00; v0.y = v01;
                    float2 v1; v1.x = v10; v1.y = v11;
                    *(float2*)(Cf + zc + (size_t)rbase * ldc + cbase)       = v0;
                    *(float2*)(Cf + zc + (size_t)(rbase + 8) * ldc + cbase) = v1;
                }
            }
        }
    }
}

// ---------------------------------------------------------------------------
// Causal softmax in place; emits bf16 hi/lo P only up to the 128-row block
// end (PV never reads beyond K = row0+128; the tail is never read).
// ---------------------------------------------------------------------------
__global__ __launch_bounds__(256) void softmax_causal(
    float* __restrict__ attn,
    __nv_bfloat16* __restrict__ Ph, __nv_bfloat16* __restrict__ Pl)
{
    const int r = blockIdx.x;
    const int h = blockIdx.y;
    const size_t ro = ((size_t)h * S_LEN + r) * S_LEN;
    float* row = attn + ro;
    const int nv  = r + 1;
    const int blockend = ((r >> 7) + 1) << 7;   // end of diagonal 128-block
    const int tid = threadIdx.x;

    float v[8];
    float mx = -1e30f;
#pragma unroll
    for (int i = 0; i < 8; i++) {
        int c = tid + i * 256;
        v[i] = (c < nv) ? row[c] : -1e30f;
        mx = fmaxf(mx, v[i]);
    }

    __shared__ float red[256];
    red[tid] = mx;
    __syncthreads();
#pragma unroll
    for (int s2 = 128; s2 > 0; s2 >>= 1) {
        if (tid < s2) red[tid] = fmaxf(red[tid], red[tid + s2]);
        __syncthreads();
    }
    mx = red[0];
    __syncthreads();

    float sum = 0.f;
#pragma unroll
    for (int i = 0; i < 8; i++) {
        int c = tid + i * 256;
        v[i] = (c < nv) ? expf(v[i] - mx) : 0.f;
        sum += v[i];
    }
    red[tid] = sum;
    __syncthreads();
#pragma unroll
    for (int s2 = 128; s2 > 0; s2 >>= 1) {
        if (tid < s2) red[tid] += red[tid + s2];
        __syncthreads();
    }
    const float inv = 1.f / red[0];

#pragma unroll
    for (int i = 0; i < 8; i++) {
        int c = tid + i * 256;
        float val = v[i] * inv;
        row[c] = val;
        if (c < blockend) {
            __nv_bfloat16 hb = __float2bfloat16(val);
            Ph[ro + c] = hb;
            Pl[ro + c] = __float2bfloat16(val - __bfloat162float(hb));
        }
    }
}

// ---------------------------------------------------------------------------
// Launch
// Inputs: hidden_states, cos, sin, attention_mask, w_qkv, w_o
// Output: [out (1,2048,3072)] ++ [attn_weights (1,24,2048,2048)]
// ---------------------------------------------------------------------------
extern "C" void kernel_launch(void* const* d_in, const int* in_sizes, int n_in,
                              void* d_out, int out_size)
{
    const float* hidden = (const float*)d_in[0];
    const float* cosb   = (const float*)d_in[1];
    const float* sinb   = (const float*)d_in[2];
    const float* wqkv   = (const float*)d_in[4];
    const float* wo     = (const float*)d_in[5];

    float* out  = (float*)d_out;
    float* attn = out + (size_t)S_LEN * HID;

    float* qkv;
    __nv_bfloat16 *hidh, *hidl, *wqkvh, *wqkvl, *woh, *wol;
    __nv_bfloat16 *qkh, *qkl, *vTh, *vTl, *Ph, *Pl, *aoh, *aol;
    cudaGetSymbolAddress((void**)&qkv,   g_qkv);
    cudaGetSymbolAddress((void**)&hidh,  g_hidh);
    cudaGetSymbolAddress((void**)&hidl,  g_hidl);
    cudaGetSymbolAddress((void**)&wqkvh, g_wqkvh);
    cudaGetSymbolAddress((void**)&wqkvl, g_wqkvl);
    cudaGetSymbolAddress((void**)&woh,   g_woh);
    cudaGetSymbolAddress((void**)&wol,   g_wol);
    cudaGetSymbolAddress((void**)&qkh,   g_qkh);
    cudaGetSymbolAddress((void**)&qkl,   g_qkl);
    cudaGetSymbolAddress((void**)&vTh,   g_vTh);
    cudaGetSymbolAddress((void**)&vTl,   g_vTl);
    cudaGetSymbolAddress((void**)&Ph,    g_Ph);
    cudaGetSymbolAddress((void**)&Pl,    g_Pl);
    cudaGetSymbolAddress((void**)&aoh,   g_aoh);
    cudaGetSymbolAddress((void**)&aol,   g_aol);

    cudaFuncSetAttribute(gemm_bf16, cudaFuncAttributeMaxDynamicSharedMemorySize,
                         GEMM_SMEM);

    // one-time side stream + events for overlapping the w_o split
    static cudaStream_t s2 = nullptr;
    static cudaEvent_t evF = nullptr, evJ = nullptr;
    if (!s2) {
        cudaStreamCreateWithFlags(&s2, cudaStreamNonBlocking);
        cudaEventCreateWithFlags(&evF, cudaEventDisableTiming);
        cudaEventCreateWithFlags(&evJ, cudaEventDisableTiming);
    }

    // fork: w_o split runs on s2, overlapped with main-stream work
    cudaEventRecord(evF, 0);
    cudaStreamWaitEvent(s2, evF, 0);
    conv_split<<<(HID * HID / 4 + 255) / 256, 256, 0, s2>>>(
        wo, woh, wol, HID * HID / 4);
    cudaEventRecord(evJ, s2);

    // 0. operand splits needed before QKV (main stream)
    conv_split<<<(S_LEN * HID / 4 + 255) / 256, 256>>>(hidden, hidh, hidl,
                                                       S_LEN * HID / 4);
    conv_split<<<(OPSZ * HID / 4 + 255) / 256, 256>>>(wqkv, wqkvh, wqkvl,
                                                      OPSZ * HID / 4);

    // 1. qkv = hidden @ w_qkv^T   (2048 x 5120, K=3072), fp32 out
    gemm_bf16<<<dim3(OPSZ / 128, S_LEN / 128, 1), 512, GEMM_SMEM>>>(
        hidh, hidl, HID, 0, wqkvh, wqkvl, HID, 0, 1,
        qkv, nullptr, nullptr, OPSZ, 0, HID, 1.0f, 0);

    // 2. RoPE + split Q/K;  3. transpose + split V
    rope_split<<<S_LEN * 1024 / 256, 256>>>(qkv, cosb, sinb, qkh, qkl);
    vsplit_T<<<dim3((NKV * HD) / 32, S_LEN / 32), dim3(32, 8)>>>(qkv, vTh, vTl);

    // 4. scores = Q K^T * scale (causal tiles only) -> attn fp32
    gemm_bf16<<<dim3(S_LEN / 128, S_LEN / 128, NH), 512, GEMM_SMEM>>>(
        qkh, qkl, QK_COLS, HD,
        qkh + HID, qkl + HID, QK_COLS, HD, 3,
        attn, nullptr, nullptr, S_LEN, (long long)S_LEN * S_LEN,
        HD, SCALING, 1);

    // 5. softmax in place + P hi/lo emit (block-limited)
    softmax_causal<<<dim3(S_LEN, NH), 256>>>(attn, Ph, Pl);

    // 6. ao(hi/lo) = P @ V   (K limited to row0+128)
    gemm_bf16<<<dim3(HD / 128, S_LEN / 128, NH), 512, GEMM_SMEM>>>(
        Ph, Pl, S_LEN, (long long)S_LEN * S_LEN,
        vTh, vTl, S_LEN, (long long)HD * S_LEN, 3,
        nullptr, aoh, aol, HID, HD,
        S_LEN, 1.0f, 2 | 4);

    // join: w_o split must be done before the out-proj GEMM
    cudaStreamWaitEvent(0, evJ, 0);

    // 7. out = ao @ w_o^T   (2048 x 3072, K=3072), fp32 out
    gemm_bf16<<<dim3(HID / 128, S_LEN / 128, 1), 512, GEMM_SMEM>>>(
        aoh, aol, HID, 0, woh, wol, HID, 0, 1,
        out, nullptr, nullptr, HID, 0, HID, 1.0f, 0);
}

// round 11
// speedup vs baseline: 1.4125x; 1.2620x over previous
#include <cuda_runtime.h>
#include <cuda_fp16.h>
#include <cstdint>

#define S_LEN 2048
#define HID 3072
#define NH 24
#define NKV 8
#define HD 128
#define OPSZ 5120
#define QK_COLS 4096
#define SCALING 0.08838834764831845f

// ---------------------------------------------------------------------------
// Scratch (__device__ globals; runtime allocation forbidden)
// ---------------------------------------------------------------------------
__device__ float  g_qkv[(size_t)S_LEN * OPSZ];                                 // 42 MB
__device__ __half g_hidh [(size_t)S_LEN * HID], g_hidl [(size_t)S_LEN * HID];
__device__ __half g_wqkvh[(size_t)OPSZ * HID];                                 // B: hi only
__device__ __half g_woh  [(size_t)HID * HID];                                  // B: hi only
__device__ __half g_qkh  [(size_t)S_LEN * QK_COLS], g_qkl[(size_t)S_LEN * QK_COLS];
__device__ __half g_vTh  [(size_t)NKV * HD * S_LEN];                           // B: hi only
__device__ __half g_Ph   [(size_t)NH * S_LEN * S_LEN];                         // 201 MB
__device__ __half g_Pl   [(size_t)NH * S_LEN * S_LEN];                         // 201 MB
__device__ __half g_aoh  [(size_t)S_LEN * HID], g_aol [(size_t)S_LEN * HID];

// ---------------------------------------------------------------------------
// helpers
// ---------------------------------------------------------------------------
__device__ __forceinline__ uint32_t smem_u32(const void* p) {
    uint32_t a;
    asm("{ .reg .u64 t; cvta.to.shared.u64 t, %1; cvt.u32.u64 %0, t; }"
        : "=r"(a) : "l"(p));
    return a;
}
__device__ __forceinline__ void ldm4(uint32_t* r, uint32_t addr) {
    asm volatile("ldmatrix.sync.aligned.m8n8.x4.shared.b16 {%0,%1,%2,%3}, [%4];"
        : "=r"(r[0]), "=r"(r[1]), "=r"(r[2]), "=r"(r[3]) : "r"(addr));
}
__device__ __forceinline__ void mma16816(float* c, const uint32_t* a,
                                         const uint32_t* b) {
    asm volatile(
        "mma.sync.aligned.m16n8k16.row.col.f32.f16.f16.f32 "
        "{%0,%1,%2,%3}, {%4,%5,%6,%7}, {%8,%9}, {%0,%1,%2,%3};"
        : "+f"(c[0]), "+f"(c[1]), "+f"(c[2]), "+f"(c[3])
        : "r"(a[0]), "r"(a[1]), "r"(a[2]), "r"(a[3]), "r"(b[0]), "r"(b[1]));
}
// pack two fp32 -> f16x2 (lo half = a, hi half = b), round-to-nearest
__device__ __forceinline__ uint32_t pk2h(float a, float b) {
    uint32_t r;
    asm("cvt.rn.f16x2.f32 %0, %1, %2;" : "=r"(r) : "f"(b), "f"(a));
    return r;
}
__device__ __forceinline__ float h2f_lo(uint32_t p) {
    return __half2float(__ushort_as_half((unsigned short)(p & 0xffffu)));
}
__device__ __forceinline__ float h2f_hi(uint32_t p) {
    return __half2float(__ushort_as_half((unsigned short)(p >> 16)));
}
#define CP16(dst, src) \
    asm volatile("cp.async.cg.shared.global [%0], [%1], 16;" \
                 :: "r"(dst), "l"(src) : "memory")
#define CP_COMMIT() asm volatile("cp.async.commit_group;" ::: "memory")
#define CP_WAIT2()  asm volatile("cp.async.wait_group 2;" ::: "memory")

// ---------------------------------------------------------------------------
// fp32 -> (f16 hi, f16 lo) split, 4 elems/thread
// ---------------------------------------------------------------------------
__global__ __launch_bounds__(256) void conv_split_hl(
    const float* __restrict__ src, __half* __restrict__ h,
    __half* __restrict__ l, int n4)
{
    int i = blockIdx.x * 256 + threadIdx.x;
    if (i >= n4) return;
    float4 x = ((const float4*)src)[i];
    uint32_t p0 = pk2h(x.x, x.y), p1 = pk2h(x.z, x.w);
    float l0 = x.x - h2f_lo(p0);
    float l1 = x.y - h2f_hi(p0);
    float l2 = x.z - h2f_lo(p1);
    float l3 = x.w - h2f_hi(p1);
    uint2 hh; hh.x = p0; hh.y = p1;
    uint2 ll; ll.x = pk2h(l0, l1); ll.y = pk2h(l2, l3);
    ((uint2*)h)[i] = hh;
    ((uint2*)l)[i] = ll;
}

// fp32 -> f16 hi only (B-side operands), 4 elems/thread
__global__ __launch_bounds__(256) void conv_split_h(
    const float* __restrict__ src, __half* __restrict__ h, int n4)
{
    int i = blockIdx.x * 256 + threadIdx.x;
    if (i >= n4) return;
    float4 x = ((const float4*)src)[i];
    uint2 hh; hh.x = pk2h(x.x, x.y); hh.y = pk2h(x.z, x.w);
    ((uint2*)h)[i] = hh;
}

// ---------------------------------------------------------------------------
// Fused RoPE + split on Q/K columns (0..4095). Q cols get hi+lo, K hi only.
// ---------------------------------------------------------------------------
__global__ __launch_bounds__(256) void rope_split(
    const float* __restrict__ qkv, const float* __restrict__ cosb,
    const float* __restrict__ sinb,
    __half* __restrict__ qh, __half* __restrict__ ql)
{
    int idx = blockIdx.x * 256 + threadIdx.x;   // S_LEN * 1024
    int s = idx >> 10;
    int c = (idx & 1023) * 4;
    int d = c & 127;
    const float* row = qkv + (size_t)s * OPSZ;
    float4 x = *(const float4*)(row + c);
    if (d < 96) {
        float4 cc = *(const float4*)(cosb + s * 96 + d);
        float4 ss = *(const float4*)(sinb + s * 96 + d);
        if (d < 48) {
            float4 p = *(const float4*)(row + c + 48);
            x.x = x.x * cc.x - p.x * ss.x;
            x.y = x.y * cc.y - p.y * ss.y;
            x.z = x.z * cc.z - p.z * ss.z;
            x.w = x.w * cc.w - p.w * ss.w;
        } else {
            float4 p = *(const float4*)(row + c - 48);
            x.x = x.x * cc.x + p.x * ss.x;
            x.y = x.y * cc.y + p.y * ss.y;
            x.z = x.z * cc.z + p.z * ss.z;
            x.w = x.w * cc.w + p.w * ss.w;
        }
    }
    uint32_t p0 = pk2h(x.x, x.y), p1 = pk2h(x.z, x.w);
    size_t o = ((size_t)s * QK_COLS + c) >> 2;
    uint2 hh; hh.x = p0; hh.y = p1;
    ((uint2*)qh)[o] = hh;
    if (c < HID) {                      // lo needed only for Q (A-side)
        float l0 = x.x - h2f_lo(p0);
        float l1 = x.y - h2f_hi(p0);
        float l2 = x.z - h2f_lo(p1);
        float l3 = x.w - h2f_hi(p1);
        uint2 ll; ll.x = pk2h(l0, l1); ll.y = pk2h(l2, l3);
        ((uint2*)ql)[o] = ll;
    }
}

// ---------------------------------------------------------------------------
// V transpose + split (hi only): vT[kv*HD+d][s] = qkv[s][4096+kv*HD+d]
// ---------------------------------------------------------------------------
__global__ __launch_bounds__(256) void vsplit_T(
    const float* __restrict__ qkv, __half* __restrict__ vh)
{
    __shared__ float tile[32][33];
    const int t0 = blockIdx.x * 32;
    const int s0 = blockIdx.y * 32;
    const int tx = threadIdx.x, ty = threadIdx.y;   // (32, 8)
#pragma unroll
    for (int j = 0; j < 4; j++)
        tile[ty + 8 * j][tx] =
            qkv[(size_t)(s0 + ty + 8 * j) * OPSZ + 4096 + t0 + tx];
    __syncthreads();
#pragma unroll
    for (int j = 0; j < 4; j++) {
        float v = tile[tx][ty + 8 * j];
        vh[(size_t)(t0 + ty + 8 * j) * S_LEN + s0 + tx] = __float2half_rn(v);
    }
}

// ---------------------------------------------------------------------------
// Generic NT GEMM, fp16 2-term: C = alpha * (Ah+Al)[M,K] * Bh[N,K]^T
// (error = A*Bl ~ 2^-12 rel, under the 1e-3 threshold with margin)
// 128x128 tile, 512 threads (16 warps, warp tile 32x32), KC=32,
// 4-stage cp.async pipeline, 80B SMEM row pitch. 2 HMMA per k16.
// flags: 1 = causal tile skip, 2 = K limited to row0+128, 4 = split output.
// ---------------------------------------------------------------------------
#define KC 32
#define TILE80 10240u              // 128 rows * 80 B
#define STAGE_B (3u * TILE80)      // Ah Al Bh = 30720
#define NSTAGE  4
#define GEMM_SMEM (NSTAGE * STAGE_B)   // 122880

__global__ __launch_bounds__(512) void gemm_f16(
    const __half* __restrict__ Ah, const __half* __restrict__ Al,
    int lda, long long sAz,
    const __half* __restrict__ Bh, int ldb, long long sBz, int kvdiv,
    float* __restrict__ Cf, __half* __restrict__ Ch,
    __half* __restrict__ Cl, int ldc, long long sCz,
    int K, float alpha, int flags)
{
    const int row0 = blockIdx.y << 7;
    const int col0 = blockIdx.x << 7;
    if ((flags & 1) && col0 > row0) return;
    const int z = blockIdx.z;
    const size_t za = (size_t)z * sAz;
    const size_t zb = (size_t)(z / kvdiv) * sBz;
    const size_t zc = (size_t)z * sCz;
    Ah += za; Al += za; Bh += zb;
    const int Keff = (flags & 2) ? ((K < row0 + 128) ? K : row0 + 128) : K;
    const int nCh  = Keff >> 5;

    extern __shared__ char smem[];
    const uint32_t base = smem_u32(smem);

    const int tid  = threadIdx.x;
    const int warp = tid >> 5;
    const int lane = tid & 31;
    const int wm   = warp >> 2;      // 0..3
    const int wn   = warp & 3;       // 0..3

    // producer mapping: row = tid>>2 (0..127), 16B chunk = tid&3
    const int prow = tid >> 2;
    const int pq   = tid & 3;
    const uint32_t pst = (uint32_t)prow * 80u + (uint32_t)pq * 16u;
    const __half* pAh = Ah + (size_t)(row0 + prow) * lda + pq * 8;
    const __half* pAl = Al + (size_t)(row0 + prow) * lda + pq * 8;
    const __half* pBh = Bh + (size_t)(col0 + prow) * ldb + pq * 8;

    // prologue: stages 0..2 (nCh >= 4 for every launch in this problem)
#pragma unroll
    for (int s = 0; s < NSTAGE - 1; s++) {
        const int kO = s * KC;
        const uint32_t st = base + (uint32_t)s * STAGE_B;
        CP16(st + pst,               pAh + kO);
        CP16(st + TILE80 + pst,      pAl + kO);
        CP16(st + 2u * TILE80 + pst, pBh + kO);
        CP_COMMIT();
    }

    // acc[mt][g] = n-subtile 2g, acc2[mt][g] = n-subtile 2g+1
    float acc [2][2][4];
    float acc2[2][2][4];
#pragma unroll
    for (int mt = 0; mt < 2; mt++)
#pragma unroll
        for (int g = 0; g < 2; g++)
#pragma unroll
            for (int r = 0; r < 4; r++) { acc[mt][g][r] = 0.f; acc2[mt][g][r] = 0.f; }

    const uint32_t aRow  = (uint32_t)(wm * 32 + (lane & 15));
    const uint32_t aSlot = (uint32_t)(lane >> 4);
    const uint32_t bRow  = (uint32_t)(wn * 32 + (lane & 7) + ((lane >> 4) << 3));
    const uint32_t bSlot = (uint32_t)((lane >> 3) & 1);

    for (int i = 0; i < nCh; i++) {
        CP_WAIT2();                 // chunk i landed
        __syncthreads();            // all warps done with the stage being refilled
        if (i + NSTAGE - 1 < nCh) {
            const int kO = (i + NSTAGE - 1) * KC;
            const uint32_t st =
                base + (uint32_t)((i + NSTAGE - 1) & (NSTAGE - 1)) * STAGE_B;
            CP16(st + pst,               pAh + kO);
            CP16(st + TILE80 + pst,      pAl + kO);
            CP16(st + 2u * TILE80 + pst, pBh + kO);
        }
        CP_COMMIT();

        const uint32_t buf = base + (uint32_t)(i & (NSTAGE - 1)) * STAGE_B;
#pragma unroll
        for (int s = 0; s < 2; s++) {
            uint32_t a[2][4];       // Ah, later overwritten by Al
            uint32_t b2[2][4];      // Bh (two subtiles per group)
            // phase 1: Ah x Bh
#pragma unroll
            for (int mt = 0; mt < 2; mt++)
                ldm4(a[mt], buf + (aRow + (uint32_t)(mt * 16)) * 80u
                                + (2u * s + aSlot) * 16u);
#pragma unroll
            for (int g = 0; g < 2; g++)
                ldm4(b2[g], buf + 2u * TILE80
                                + (bRow + (uint32_t)(g * 16)) * 80u
                                + (2u * s + bSlot) * 16u);
#pragma unroll
            for (int mt = 0; mt < 2; mt++)
#pragma unroll
                for (int g = 0; g < 2; g++) {
                    mma16816(acc [mt][g], a[mt], b2[g]);
                    mma16816(acc2[mt][g], a[mt], b2[g] + 2);
                }
            // phase 2: Al x Bh (overwrite a)
#pragma unroll
            for (int mt = 0; mt < 2; mt++)
                ldm4(a[mt], buf + TILE80
                                + (aRow + (uint32_t)(mt * 16)) * 80u
                                + (2u * s + aSlot) * 16u);
#pragma unroll
            for (int mt = 0; mt < 2; mt++)
#pragma unroll
                for (int g = 0; g < 2; g++) {
                    mma16816(acc [mt][g], a[mt], b2[g]);
                    mma16816(acc2[mt][g], a[mt], b2[g] + 2);
                }
        }
    }

    // epilogue: group g covers n-subtiles {2g (acc), 2g+1 (acc2)}
#pragma unroll
    for (int mt = 0; mt < 2; mt++) {
        const int rbase = row0 + wm * 32 + mt * 16 + (lane >> 2);
#pragma unroll
        for (int g = 0; g < 2; g++) {
#pragma unroll
            for (int half = 0; half < 2; half++) {
                const float* a4 = half ? acc2[mt][g] : acc[mt][g];
                const int nt = 2 * g + half;
                const int cbase = col0 + wn * 32 + nt * 8 + (lane & 3) * 2;
                float v00 = alpha * a4[0];
                float v01 = alpha * a4[1];
                float v10 = alpha * a4[2];
                float v11 = alpha * a4[3];
                if (flags & 4) {
                    uint32_t h0 = pk2h(v00, v01);
                    uint32_t l0 = pk2h(v00 - h2f_lo(h0), v01 - h2f_hi(h0));
                    uint32_t h1 = pk2h(v10, v11);
                    uint32_t l1 = pk2h(v10 - h2f_lo(h1), v11 - h2f_hi(h1));
                    *(uint32_t*)(Ch + zc + (size_t)rbase * ldc + cbase)       = h0;
                    *(uint32_t*)(Cl + zc + (size_t)rbase * ldc + cbase)       = l0;
                    *(uint32_t*)(Ch + zc + (size_t)(rbase + 8) * ldc + cbase) = h1;
                    *(uint32_t*)(Cl + zc + (size_t)(rbase + 8) * ldc + cbase) = l1;
                } else {
                    float2 v0; v0.x = v00; v0.y = v01;
                    float2 v1; v1.x = v10; v1.y = v11;
                    *(float2*)(Cf + zc + (size_t)rbase * ldc + cbase)       = v0;
                    *(float2*)(Cf + zc + (size_t)(rbase + 8) * ldc + cbase) = v1;
                }
            }
        }
    }
}

// ---------------------------------------------------------------------------
// Causal softmax in place; emits f16 hi/lo P only up to the 128-row block end.
// ---------------------------------------------------------------------------
__global__ __launch_bounds__(256) void softmax_causal(
    float* __restrict__ attn,
    __half* __restrict__ Ph, __half* __restrict__ Pl)
{
    const int r = blockIdx.x;
    const int h = blockIdx.y;
    const size_t ro = ((size_t)h * S_LEN + r) * S_LEN;
    float* row = attn + ro;
    const int nv  = r + 1;
    const int blockend = ((r >> 7) + 1) << 7;   // end of diagonal 128-block
    const int tid = threadIdx.x;

    float v[8];
    float mx = -1e30f;
#pragma unroll
    for (int i = 0; i < 8; i++) {
        int c = tid + i * 256;
        v[i] = (c < nv) ? row[c] : -1e30f;
        mx = fmaxf(mx, v[i]);
    }

    __shared__ float red[256];
    red[tid] = mx;
    __syncthreads();
#pragma unroll
    for (int s2 = 128; s2 > 0; s2 >>= 1) {
        if (tid < s2) red[tid] = fmaxf(red[tid], red[tid + s2]);
        __syncthreads();
    }
    mx = red[0];
    __syncthreads();

    float sum = 0.f;
#pragma unroll
    for (int i = 0; i < 8; i++) {
        int c = tid + i * 256;
        v[i] = (c < nv) ? expf(v[i] - mx) : 0.f;
        sum += v[i];
    }
    red[tid] = sum;
    __syncthreads();
#pragma unroll
    for (int s2 = 128; s2 > 0; s2 >>= 1) {
        if (tid < s2) red[tid] += red[tid + s2];
        __syncthreads();
    }
    const float inv = 1.f / red[0];

#pragma unroll
    for (int i = 0; i < 8; i++) {
        int c = tid + i * 256;
        float val = v[i] * inv;
        row[c] = val;
        if (c < blockend) {
            __half hb = __float2half_rn(val);
            Ph[ro + c] = hb;
            Pl[ro + c] = __float2half_rn(val - __half2float(hb));
        }
    }
}

// ---------------------------------------------------------------------------
// Launch
// Inputs: hidden_states, cos, sin, attention_mask, w_qkv, w_o
// Output: [out (1,2048,3072)] ++ [attn_weights (1,24,2048,2048)]
// ---------------------------------------------------------------------------
extern "C" void kernel_launch(void* const* d_in, const int* in_sizes, int n_in,
                              void* d_out, int out_size)
{
    const float* hidden = (const float*)d_in[0];
    const float* cosb   = (const float*)d_in[1];
    const float* sinb   = (const float*)d_in[2];
    const float* wqkv   = (const float*)d_in[4];
    const float* wo     = (const float*)d_in[5];

    float* out  = (float*)d_out;
    float* attn = out + (size_t)S_LEN * HID;

    float* qkv;
    __half *hidh, *hidl, *wqkvh, *woh;
    __half *qkh, *qkl, *vTh, *Ph, *Pl, *aoh, *aol;
    cudaGetSymbolAddress((void**)&qkv,   g_qkv);
    cudaGetSymbolAddress((void**)&hidh,  g_hidh);
    cudaGetSymbolAddress((void**)&hidl,  g_hidl);
    cudaGetSymbolAddress((void**)&wqkvh, g_wqkvh);
    cudaGetSymbolAddress((void**)&woh,   g_woh);
    cudaGetSymbolAddress((void**)&qkh,   g_qkh);
    cudaGetSymbolAddress((void**)&qkl,   g_qkl);
    cudaGetSymbolAddress((void**)&vTh,   g_vTh);
    cudaGetSymbolAddress((void**)&Ph,    g_Ph);
    cudaGetSymbolAddress((void**)&Pl,    g_Pl);
    cudaGetSymbolAddress((void**)&aoh,   g_aoh);
    cudaGetSymbolAddress((void**)&aol,   g_aol);

    cudaFuncSetAttribute(gemm_f16, cudaFuncAttributeMaxDynamicSharedMemorySize,
                         GEMM_SMEM);

    // one-time side stream + events for overlapping the w_o split
    static cudaStream_t s2 = nullptr;
    static cudaEvent_t evF = nullptr, evJ = nullptr;
    if (!s2) {
        cudaStreamCreateWithFlags(&s2, cudaStreamNonBlocking);
        cudaEventCreateWithFlags(&evF, cudaEventDisableTiming);
        cudaEventCreateWithFlags(&evJ, cudaEventDisableTiming);
    }

    // fork: w_o split runs on s2, overlapped with main-stream work
    cudaEventRecord(evF, 0);
    cudaStreamWaitEvent(s2, evF, 0);
    conv_split_h<<<(HID * HID / 4 + 255) / 256, 256, 0, s2>>>(
        wo, woh, HID * HID / 4);
    cudaEventRecord(evJ, s2);

    // 0. operand splits needed before QKV (main stream)
    conv_split_hl<<<(S_LEN * HID / 4 + 255) / 256, 256>>>(hidden, hidh, hidl,
                                                          S_LEN * HID / 4);
    conv_split_h<<<(OPSZ * HID / 4 + 255) / 256, 256>>>(wqkv, wqkvh,
                                                        OPSZ * HID / 4);

    // 1. qkv = hidden @ w_qkv^T   (2048 x 5120, K=3072), fp32 out
    gemm_f16<<<dim3(OPSZ / 128, S_LEN / 128, 1), 512, GEMM_SMEM>>>(
        hidh, hidl, HID, 0, wqkvh, HID, 0, 1,
        qkv, nullptr, nullptr, OPSZ, 0, HID, 1.0f, 0);

    // 2. RoPE + split Q(hi/lo)/K(hi);  3. transpose + split V (hi)
    rope_split<<<S_LEN * 1024 / 256, 256>>>(qkv, cosb, sinb, qkh, qkl);
    vsplit_T<<<dim3((NKV * HD) / 32, S_LEN / 32), dim3(32, 8)>>>(qkv, vTh);

    // 4. scores = Q K^T * scale (causal tiles only) -> attn fp32
    gemm_f16<<<dim3(S_LEN / 128, S_LEN / 128, NH), 512, GEMM_SMEM>>>(
        qkh, qkl, QK_COLS, HD,
        qkh + HID, QK_COLS, HD, 3,
        attn, nullptr, nullptr, S_LEN, (long long)S_LEN * S_LEN,
        HD, SCALING, 1);

    // 5. softmax in place + P hi/lo emit (block-limited)
    softmax_causal<<<dim3(S_LEN, NH), 256>>>(attn, Ph, Pl);

    // 6. ao(hi/lo) = P @ V   (K limited to row0+128)
    gemm_f16<<<dim3(HD / 128, S_LEN / 128, NH), 512, GEMM_SMEM>>>(
        Ph, Pl, S_LEN, (long long)S_LEN * S_LEN,
        vTh, S_LEN, (long long)HD * S_LEN, 3,
        nullptr, aoh, aol, HID, HD,
        S_LEN, 1.0f, 2 | 4);

    // join: w_o split must be done before the out-proj GEMM
    cudaStreamWaitEvent(0, evJ, 0);

    // 7. out = ao @ w_o^T   (2048 x 3072, K=3072), fp32 out
    gemm_f16<<<dim3(HID / 128, S_LEN / 128, 1), 512, GEMM_SMEM>>>(
        aoh, aol, HID, 0, woh, HID, 0, 1,
        out, nullptr, nullptr, HID, 0, HID, 1.0f, 0);
}

// round 12
// speedup vs baseline: 1.5787x; 1.1176x over previous
#include <cuda_runtime.h>
#include <cuda_fp16.h>
#include <cstdint>

#define S_LEN 2048
#define HID 3072
#define NH 24
#define NKV 8
#define HD 128
#define OPSZ 5120
#define QK_COLS 4096
#define SCALING 0.08838834764831845f

// ---------------------------------------------------------------------------
// Scratch (__device__ globals; runtime allocation forbidden)
// ---------------------------------------------------------------------------
__device__ float  g_qkv[(size_t)S_LEN * OPSZ];                                 // 42 MB
__device__ __half g_hidh [(size_t)S_LEN * HID], g_hidl [(size_t)S_LEN * HID];
__device__ __half g_wqkvh[(size_t)OPSZ * HID];                                 // B: hi only
__device__ __half g_woh  [(size_t)HID * HID];                                  // B: hi only
__device__ __half g_qkh  [(size_t)S_LEN * QK_COLS], g_qkl[(size_t)S_LEN * QK_COLS];
__device__ __half g_vTh  [(size_t)NKV * HD * S_LEN];                           // B: hi only
__device__ __half g_Ph   [(size_t)NH * S_LEN * S_LEN];                         // 201 MB (hi only)
__device__ __half g_aoh  [(size_t)S_LEN * HID], g_aol [(size_t)S_LEN * HID];

// ---------------------------------------------------------------------------
// helpers
// ---------------------------------------------------------------------------
__device__ __forceinline__ uint32_t smem_u32(const void* p) {
    uint32_t a;
    asm("{ .reg .u64 t; cvta.to.shared.u64 t, %1; cvt.u32.u64 %0, t; }"
        : "=r"(a) : "l"(p));
    return a;
}
__device__ __forceinline__ void ldm4(uint32_t* r, uint32_t addr) {
    asm volatile("ldmatrix.sync.aligned.m8n8.x4.shared.b16 {%0,%1,%2,%3}, [%4];"
        : "=r"(r[0]), "=r"(r[1]), "=r"(r[2]), "=r"(r[3]) : "r"(addr));
}
__device__ __forceinline__ void mma16816(float* c, const uint32_t* a,
                                         const uint32_t* b) {
    asm volatile(
        "mma.sync.aligned.m16n8k16.row.col.f32.f16.f16.f32 "
        "{%0,%1,%2,%3}, {%4,%5,%6,%7}, {%8,%9}, {%0,%1,%2,%3};"
        : "+f"(c[0]), "+f"(c[1]), "+f"(c[2]), "+f"(c[3])
        : "r"(a[0]), "r"(a[1]), "r"(a[2]), "r"(a[3]), "r"(b[0]), "r"(b[1]));
}
// pack two fp32 -> f16x2 (lo half = a, hi half = b), round-to-nearest
__device__ __forceinline__ uint32_t pk2h(float a, float b) {
    uint32_t r;
    asm("cvt.rn.f16x2.f32 %0, %1, %2;" : "=r"(r) : "f"(b), "f"(a));
    return r;
}
__device__ __forceinline__ float h2f_lo(uint32_t p) {
    return __half2float(__ushort_as_half((unsigned short)(p & 0xffffu)));
}
__device__ __forceinline__ float h2f_hi(uint32_t p) {
    return __half2float(__ushort_as_half((unsigned short)(p >> 16)));
}
#define CP16(dst, src) \
    asm volatile("cp.async.cg.shared.global [%0], [%1], 16;" \
                 :: "r"(dst), "l"(src) : "memory")
#define CP_COMMIT() asm volatile("cp.async.commit_group;" ::: "memory")
#define CP_WAIT2()  asm volatile("cp.async.wait_group 2;" ::: "memory")

// ---------------------------------------------------------------------------
// fp32 -> (f16 hi, f16 lo) split, 4 elems/thread
// ---------------------------------------------------------------------------
__global__ __launch_bounds__(256) void conv_split_hl(
    const float* __restrict__ src, __half* __restrict__ h,
    __half* __restrict__ l, int n4)
{
    int i = blockIdx.x * 256 + threadIdx.x;
    if (i >= n4) return;
    float4 x = ((const float4*)src)[i];
    uint32_t p0 = pk2h(x.x, x.y), p1 = pk2h(x.z, x.w);
    float l0 = x.x - h2f_lo(p0);
    float l1 = x.y - h2f_hi(p0);
    float l2 = x.z - h2f_lo(p1);
    float l3 = x.w - h2f_hi(p1);
    uint2 hh; hh.x = p0; hh.y = p1;
    uint2 ll; ll.x = pk2h(l0, l1); ll.y = pk2h(l2, l3);
    ((uint2*)h)[i] = hh;
    ((uint2*)l)[i] = ll;
}

// fp32 -> f16 hi only (B-side operands), 4 elems/thread
__global__ __launch_bounds__(256) void conv_split_h(
    const float* __restrict__ src, __half* __restrict__ h, int n4)
{
    int i = blockIdx.x * 256 + threadIdx.x;
    if (i >= n4) return;
    float4 x = ((const float4*)src)[i];
    uint2 hh; hh.x = pk2h(x.x, x.y); hh.y = pk2h(x.z, x.w);
    ((uint2*)h)[i] = hh;
}

// ---------------------------------------------------------------------------
// Fused RoPE + split on Q/K columns (0..4095). Q cols get hi+lo, K hi only.
// ---------------------------------------------------------------------------
__global__ __launch_bounds__(256) void rope_split(
    const float* __restrict__ qkv, const float* __restrict__ cosb,
    const float* __restrict__ sinb,
    __half* __restrict__ qh, __half* __restrict__ ql)
{
    int idx = blockIdx.x * 256 + threadIdx.x;   // S_LEN * 1024
    int s = idx >> 10;
    int c = (idx & 1023) * 4;
    int d = c & 127;
    const float* row = qkv + (size_t)s * OPSZ;
    float4 x = *(const float4*)(row + c);
    if (d < 96) {
        float4 cc = *(const float4*)(cosb + s * 96 + d);
        float4 ss = *(const float4*)(sinb + s * 96 + d);
        if (d < 48) {
            float4 p = *(const float4*)(row + c + 48);
            x.x = x.x * cc.x - p.x * ss.x;
            x.y = x.y * cc.y - p.y * ss.y;
            x.z = x.z * cc.z - p.z * ss.z;
            x.w = x.w * cc.w - p.w * ss.w;
        } else {
            float4 p = *(const float4*)(row + c - 48);
            x.x = x.x * cc.x + p.x * ss.x;
            x.y = x.y * cc.y + p.y * ss.y;
            x.z = x.z * cc.z + p.z * ss.z;
            x.w = x.w * cc.w + p.w * ss.w;
        }
    }
    uint32_t p0 = pk2h(x.x, x.y), p1 = pk2h(x.z, x.w);
    size_t o = ((size_t)s * QK_COLS + c) >> 2;
    uint2 hh; hh.x = p0; hh.y = p1;
    ((uint2*)qh)[o] = hh;
    if (c < HID) {                      // lo needed only for Q (A-side)
        float l0 = x.x - h2f_lo(p0);
        float l1 = x.y - h2f_hi(p0);
        float l2 = x.z - h2f_lo(p1);
        float l3 = x.w - h2f_hi(p1);
        uint2 ll; ll.x = pk2h(l0, l1); ll.y = pk2h(l2, l3);
        ((uint2*)ql)[o] = ll;
    }
}

// ---------------------------------------------------------------------------
// V transpose + split (hi only): vT[kv*HD+d][s] = qkv[s][4096+kv*HD+d]
// ---------------------------------------------------------------------------
__global__ __launch_bounds__(256) void vsplit_T(
    const float* __restrict__ qkv, __half* __restrict__ vh)
{
    __shared__ float tile[32][33];
    const int t0 = blockIdx.x * 32;
    const int s0 = blockIdx.y * 32;
    const int tx = threadIdx.x, ty = threadIdx.y;   // (32, 8)
#pragma unroll
    for (int j = 0; j < 4; j++)
        tile[ty + 8 * j][tx] =
            qkv[(size_t)(s0 + ty + 8 * j) * OPSZ + 4096 + t0 + tx];
    __syncthreads();
#pragma unroll
    for (int j = 0; j < 4; j++) {
        float v = tile[tx][ty + 8 * j];
        vh[(size_t)(t0 + ty + 8 * j) * S_LEN + s0 + tx] = __float2half_rn(v);
    }
}

// ---------------------------------------------------------------------------
// Generic NT GEMM, fp16: C = alpha * (Ah [+Al]) [M,K] * Bh[N,K]^T
// Al term applied only for tiles with col0 < nloCols (per-tile term count).
// 128x128 tile, 512 threads (16 warps, warp tile 32x32), KC=32,
// 4-stage cp.async pipeline, 80B SMEM row pitch.
// flags: 1 = causal tile skip, 2 = K limited to row0+128, 4 = split output.
// ---------------------------------------------------------------------------
#define KC 32
#define TILE80 10240u              // 128 rows * 80 B
#define STAGE_B (3u * TILE80)      // Ah Al Bh = 30720
#define NSTAGE  4
#define GEMM_SMEM (NSTAGE * STAGE_B)   // 122880

__global__ __launch_bounds__(512) void gemm_f16(
    const __half* __restrict__ Ah, const __half* __restrict__ Al,
    int lda, long long sAz,
    const __half* __restrict__ Bh, int ldb, long long sBz, int kvdiv,
    float* __restrict__ Cf, __half* __restrict__ Ch,
    __half* __restrict__ Cl, int ldc, long long sCz,
    int K, float alpha, int flags, int nloCols)
{
    const int row0 = blockIdx.y << 7;
    const int col0 = blockIdx.x << 7;
    if ((flags & 1) && col0 > row0) return;
    const bool useAl = (col0 < nloCols);
    const int z = blockIdx.z;
    const size_t za = (size_t)z * sAz;
    const size_t zb = (size_t)(z / kvdiv) * sBz;
    const size_t zc = (size_t)z * sCz;
    Ah += za; Al += za; Bh += zb;
    const int Keff = (flags & 2) ? ((K < row0 + 128) ? K : row0 + 128) : K;
    const int nCh  = Keff >> 5;

    extern __shared__ char smem[];
    const uint32_t base = smem_u32(smem);

    const int tid  = threadIdx.x;
    const int warp = tid >> 5;
    const int lane = tid & 31;
    const int wm   = warp >> 2;      // 0..3
    const int wn   = warp & 3;       // 0..3

    // producer mapping: row = tid>>2 (0..127), 16B chunk = tid&3
    const int prow = tid >> 2;
    const int pq   = tid & 3;
    const uint32_t pst = (uint32_t)prow * 80u + (uint32_t)pq * 16u;
    const __half* pAh = Ah + (size_t)(row0 + prow) * lda + pq * 8;
    const __half* pAl = Al + (size_t)(row0 + prow) * lda + pq * 8;
    const __half* pBh = Bh + (size_t)(col0 + prow) * ldb + pq * 8;

    // prologue: stages 0..2 (nCh >= 4 for every launch in this problem)
#pragma unroll
    for (int s = 0; s < NSTAGE - 1; s++) {
        const int kO = s * KC;
        const uint32_t st = base + (uint32_t)s * STAGE_B;
        CP16(st + pst,               pAh + kO);
        if (useAl) CP16(st + TILE80 + pst, pAl + kO);
        CP16(st + 2u * TILE80 + pst, pBh + kO);
        CP_COMMIT();
    }

    // acc[mt][g] = n-subtile 2g, acc2[mt][g] = n-subtile 2g+1
    float acc [2][2][4];
    float acc2[2][2][4];
#pragma unroll
    for (int mt = 0; mt < 2; mt++)
#pragma unroll
        for (int g = 0; g < 2; g++)
#pragma unroll
            for (int r = 0; r < 4; r++) { acc[mt][g][r] = 0.f; acc2[mt][g][r] = 0.f; }

    const uint32_t aRow  = (uint32_t)(wm * 32 + (lane & 15));
    const uint32_t aSlot = (uint32_t)(lane >> 4);
    const uint32_t bRow  = (uint32_t)(wn * 32 + (lane & 7) + ((lane >> 4) << 3));
    const uint32_t bSlot = (uint32_t)((lane >> 3) & 1);

    for (int i = 0; i < nCh; i++) {
        CP_WAIT2();                 // chunk i landed
        __syncthreads();            // all warps done with the stage being refilled
        if (i + NSTAGE - 1 < nCh) {
            const int kO = (i + NSTAGE - 1) * KC;
            const uint32_t st =
                base + (uint32_t)((i + NSTAGE - 1) & (NSTAGE - 1)) * STAGE_B;
            CP16(st + pst,               pAh + kO);
            if (useAl) CP16(st + TILE80 + pst, pAl + kO);
            CP16(st + 2u * TILE80 + pst, pBh + kO);
        }
        CP_COMMIT();

        const uint32_t buf = base + (uint32_t)(i & (NSTAGE - 1)) * STAGE_B;
#pragma unroll
        for (int s = 0; s < 2; s++) {
            uint32_t a[2][4];       // Ah, later overwritten by Al
            uint32_t b2[2][4];      // Bh (two subtiles per group)
            // phase 1: Ah x Bh
#pragma unroll
            for (int mt = 0; mt < 2; mt++)
                ldm4(a[mt], buf + (aRow + (uint32_t)(mt * 16)) * 80u
                                + (2u * s + aSlot) * 16u);
#pragma unroll
            for (int g = 0; g < 2; g++)
                ldm4(b2[g], buf + 2u * TILE80
                                + (bRow + (uint32_t)(g * 16)) * 80u
                                + (2u * s + bSlot) * 16u);
#pragma unroll
            for (int mt = 0; mt < 2; mt++)
#pragma unroll
                for (int g = 0; g < 2; g++) {
                    mma16816(acc [mt][g], a[mt], b2[g]);
                    mma16816(acc2[mt][g], a[mt], b2[g] + 2);
                }
            // phase 2: Al x Bh (only when this tile carries the lo term)
            if (useAl) {
#pragma unroll
                for (int mt = 0; mt < 2; mt++)
                    ldm4(a[mt], buf + TILE80
                                    + (aRow + (uint32_t)(mt * 16)) * 80u
                                    + (2u * s + aSlot) * 16u);
#pragma unroll
                for (int mt = 0; mt < 2; mt++)
#pragma unroll
                    for (int g = 0; g < 2; g++) {
                        mma16816(acc [mt][g], a[mt], b2[g]);
                        mma16816(acc2[mt][g], a[mt], b2[g] + 2);
                    }
            }
        }
    }

    // epilogue: group g covers n-subtiles {2g (acc), 2g+1 (acc2)}
#pragma unroll
    for (int mt = 0; mt < 2; mt++) {
        const int rbase = row0 + wm * 32 + mt * 16 + (lane >> 2);
#pragma unroll
        for (int g = 0; g < 2; g++) {
#pragma unroll
            for (int half = 0; half < 2; half++) {
                const float* a4 = half ? acc2[mt][g] : acc[mt][g];
                const int nt = 2 * g + half;
                const int cbase = col0 + wn * 32 + nt * 8 + (lane & 3) * 2;
                float v00 = alpha * a4[0];
                float v01 = alpha * a4[1];
                float v10 = alpha * a4[2];
                float v11 = alpha * a4[3];
                if (flags & 4) {
                    uint32_t h0 = pk2h(v00, v01);
                    uint32_t l0 = pk2h(v00 - h2f_lo(h0), v01 - h2f_hi(h0));
                    uint32_t h1 = pk2h(v10, v11);
                    uint32_t l1 = pk2h(v10 - h2f_lo(h1), v11 - h2f_hi(h1));
                    *(uint32_t*)(Ch + zc + (size_t)rbase * ldc + cbase)       = h0;
                    *(uint32_t*)(Cl + zc + (size_t)rbase * ldc + cbase)       = l0;
                    *(uint32_t*)(Ch + zc + (size_t)(rbase + 8) * ldc + cbase) = h1;
                    *(uint32_t*)(Cl + zc + (size_t)(rbase + 8) * ldc + cbase) = l1;
                } else {
                    float2 v0; v0.x = v00; v0.y = v01;
                    float2 v1; v1.x = v10; v1.y = v11;
                    *(float2*)(Cf + zc + (size_t)rbase * ldc + cbase)       = v0;
                    *(float2*)(Cf + zc + (size_t)(rbase + 8) * ldc + cbase) = v1;
                }
            }
        }
    }
}

// ---------------------------------------------------------------------------
// Causal softmax in place; emits f16 P (hi only) up to the 128-row block end.
// ---------------------------------------------------------------------------
__global__ __launch_bounds__(256) void softmax_causal(
    float* __restrict__ attn, __half* __restrict__ Ph)
{
    const int r = blockIdx.x;
    const int h = blockIdx.y;
    const size_t ro = ((size_t)h * S_LEN + r) * S_LEN;
    float* row = attn + ro;
    const int nv  = r + 1;
    const int blockend = ((r >> 7) + 1) << 7;   // end of diagonal 128-block
    const int tid = threadIdx.x;

    float v[8];
    float mx = -1e30f;
#pragma unroll
    for (int i = 0; i < 8; i++) {
        int c = tid + i * 256;
        v[i] = (c < nv) ? row[c] : -1e30f;
        mx = fmaxf(mx, v[i]);
    }

    __shared__ float red[256];
    red[tid] = mx;
    __syncthreads();
#pragma unroll
    for (int s2 = 128; s2 > 0; s2 >>= 1) {
        if (tid < s2) red[tid] = fmaxf(red[tid], red[tid + s2]);
        __syncthreads();
    }
    mx = red[0];
    __syncthreads();

    float sum = 0.f;
#pragma unroll
    for (int i = 0; i < 8; i++) {
        int c = tid + i * 256;
        v[i] = (c < nv) ? expf(v[i] - mx) : 0.f;
        sum += v[i];
    }
    red[tid] = sum;
    __syncthreads();
#pragma unroll
    for (int s2 = 128; s2 > 0; s2 >>= 1) {
        if (tid < s2) red[tid] += red[tid + s2];
        __syncthreads();
    }
    const float inv = 1.f / red[0];

#pragma unroll
    for (int i = 0; i < 8; i++) {
        int c = tid + i * 256;
        float val = v[i] * inv;
        row[c] = val;
        if (c < blockend) Ph[ro + c] = __float2half_rn(val);
    }
}

// ---------------------------------------------------------------------------
// Launch
// Inputs: hidden_states, cos, sin, attention_mask, w_qkv, w_o
// Output: [out (1,2048,3072)] ++ [attn_weights (1,24,2048,2048)]
// ---------------------------------------------------------------------------
extern "C" void kernel_launch(void* const* d_in, const int* in_sizes, int n_in,
                              void* d_out, int out_size)
{
    const float* hidden = (const float*)d_in[0];
    const float* cosb   = (const float*)d_in[1];
    const float* sinb   = (const float*)d_in[2];
    const float* wqkv   = (const float*)d_in[4];
    const float* wo     = (const float*)d_in[5];

    float* out  = (float*)d_out;
    float* attn = out + (size_t)S_LEN * HID;

    float* qkv;
    __half *hidh, *hidl, *wqkvh, *woh;
    __half *qkh, *qkl, *vTh, *Ph, *aoh, *aol;
    cudaGetSymbolAddress((void**)&qkv,   g_qkv);
    cudaGetSymbolAddress((void**)&hidh,  g_hidh);
    cudaGetSymbolAddress((void**)&hidl,  g_hidl);
    cudaGetSymbolAddress((void**)&wqkvh, g_wqkvh);
    cudaGetSymbolAddress((void**)&woh,   g_woh);
    cudaGetSymbolAddress((void**)&qkh,   g_qkh);
    cudaGetSymbolAddress((void**)&qkl,   g_qkl);
    cudaGetSymbolAddress((void**)&vTh,   g_vTh);
    cudaGetSymbolAddress((void**)&Ph,    g_Ph);
    cudaGetSymbolAddress((void**)&aoh,   g_aoh);
    cudaGetSymbolAddress((void**)&aol,   g_aol);

    cudaFuncSetAttribute(gemm_f16, cudaFuncAttributeMaxDynamicSharedMemorySize,
                         GEMM_SMEM);

    // one-time side stream + events for overlapping the w_o split
    static cudaStream_t s2 = nullptr;
    static cudaEvent_t evF = nullptr, evJ = nullptr;
    if (!s2) {
        cudaStreamCreateWithFlags(&s2, cudaStreamNonBlocking);
        cudaEventCreateWithFlags(&evF, cudaEventDisableTiming);
        cudaEventCreateWithFlags(&evJ, cudaEventDisableTiming);
    }

    // fork: w_o split runs on s2, overlapped with main-stream work
    cudaEventRecord(evF, 0);
    cudaStreamWaitEvent(s2, evF, 0);
    conv_split_h<<<(HID * HID / 4 + 255) / 256, 256, 0, s2>>>(
        wo, woh, HID * HID / 4);
    cudaEventRecord(evJ, s2);

    // 0. operand splits needed before QKV (main stream)
    conv_split_hl<<<(S_LEN * HID / 4 + 255) / 256, 256>>>(hidden, hidh, hidl,
                                                          S_LEN * HID / 4);
    conv_split_h<<<(OPSZ * HID / 4 + 255) / 256, 256>>>(wqkv, wqkvh,
                                                        OPSZ * HID / 4);

    // 1. qkv = hidden @ w_qkv^T   (2048 x 5120, K=3072), fp32 out
    //    Q tiles (col0 < 3072): hi+lo A; K/V tiles: hi-only A.
    gemm_f16<<<dim3(OPSZ / 128, S_LEN / 128, 1), 512, GEMM_SMEM>>>(
        hidh, hidl, HID, 0, wqkvh, HID, 0, 1,
        qkv, nullptr, nullptr, OPSZ, 0, HID, 1.0f, 0, HID);

    // 2. RoPE + split Q(hi/lo)/K(hi);  3. transpose + split V (hi)
    rope_split<<<S_LEN * 1024 / 256, 256>>>(qkv, cosb, sinb, qkh, qkl);
    vsplit_T<<<dim3((NKV * HD) / 32, S_LEN / 32), dim3(32, 8)>>>(qkv, vTh);

    // 4. scores = Q K^T * scale (causal tiles only) -> attn fp32 (2-term A)
    gemm_f16<<<dim3(S_LEN / 128, S_LEN / 128, NH), 512, GEMM_SMEM>>>(
        qkh, qkl, QK_COLS, HD,
        qkh + HID, QK_COLS, HD, 3,
        attn, nullptr, nullptr, S_LEN, (long long)S_LEN * S_LEN,
        HD, SCALING, 1, 1 << 30);

    // 5. softmax in place + P hi emit (block-limited)
    softmax_causal<<<dim3(S_LEN, NH), 256>>>(attn, Ph);

    // 6. ao(hi/lo) = P @ V   (K limited to row0+128; P hi-only -> 1 term)
    gemm_f16<<<dim3(HD / 128, S_LEN / 128, NH), 512, GEMM_SMEM>>>(
        Ph, Ph, S_LEN, (long long)S_LEN * S_LEN,
        vTh, S_LEN, (long long)HD * S_LEN, 3,
        nullptr, aoh, aol, HID, HD,
        S_LEN, 1.0f, 2 | 4, 0);

    // join: w_o split must be done before the out-proj GEMM
    cudaStreamWaitEvent(0, evJ, 0);

    // 7. out = ao @ w_o^T   (2048 x 3072, K=3072), fp32 out (2-term A)
    gemm_f16<<<dim3(HID / 128, S_LEN / 128, 1), 512, GEMM_SMEM>>>(
        aoh, aol, HID, 0, woh, HID, 0, 1,
        out, nullptr, nullptr, HID, 0, HID, 1.0f, 0, 1 << 30);
}

// round 13
// speedup vs baseline: 1.7709x; 1.1217x over previous
#include <cuda_runtime.h>
#include <cuda_fp16.h>
#include <cstdint>

#define S_LEN 2048
#define HID 3072
#define NH 24
#define NKV 8
#define HD 128
#define OPSZ 5120
#define QK_COLS 4096
#define SCALING 0.08838834764831845f

// ---------------------------------------------------------------------------
// Scratch (__device__ globals; runtime allocation forbidden)
// ---------------------------------------------------------------------------
__device__ float  g_qkv[(size_t)S_LEN * OPSZ];                                 // 42 MB
__device__ __half g_hidh [(size_t)S_LEN * HID], g_hidl [(size_t)S_LEN * HID];
__device__ __half g_wqkvh[(size_t)OPSZ * HID];                                 // B: hi only
__device__ __half g_woh  [(size_t)HID * HID];                                  // B: hi only
__device__ __half g_qkh  [(size_t)S_LEN * QK_COLS], g_qkl[(size_t)S_LEN * QK_COLS];
__device__ __half g_vTh  [(size_t)NKV * HD * S_LEN];                           // B: hi only
__device__ __half g_Ph   [(size_t)NH * S_LEN * S_LEN];                         // 201 MB (hi only)
__device__ __half g_aoh  [(size_t)S_LEN * HID];                                // hi only

// ---------------------------------------------------------------------------
// helpers
// ---------------------------------------------------------------------------
__device__ __forceinline__ uint32_t smem_u32(const void* p) {
    uint32_t a;
    asm("{ .reg .u64 t; cvta.to.shared.u64 t, %1; cvt.u32.u64 %0, t; }"
        : "=r"(a) : "l"(p));
    return a;
}
__device__ __forceinline__ void ldm4(uint32_t* r, uint32_t addr) {
    asm volatile("ldmatrix.sync.aligned.m8n8.x4.shared.b16 {%0,%1,%2,%3}, [%4];"
        : "=r"(r[0]), "=r"(r[1]), "=r"(r[2]), "=r"(r[3]) : "r"(addr));
}
__device__ __forceinline__ void mma16816(float* c, const uint32_t* a,
                                         const uint32_t* b) {
    asm volatile(
        "mma.sync.aligned.m16n8k16.row.col.f32.f16.f16.f32 "
        "{%0,%1,%2,%3}, {%4,%5,%6,%7}, {%8,%9}, {%0,%1,%2,%3};"
        : "+f"(c[0]), "+f"(c[1]), "+f"(c[2]), "+f"(c[3])
        : "r"(a[0]), "r"(a[1]), "r"(a[2]), "r"(a[3]), "r"(b[0]), "r"(b[1]));
}
// pack two fp32 -> f16x2 (lo half = a, hi half = b), round-to-nearest
__device__ __forceinline__ uint32_t pk2h(float a, float b) {
    uint32_t r;
    asm("cvt.rn.f16x2.f32 %0, %1, %2;" : "=r"(r) : "f"(b), "f"(a));
    return r;
}
__device__ __forceinline__ float h2f_lo(uint32_t p) {
    return __half2float(__ushort_as_half((unsigned short)(p & 0xffffu)));
}
__device__ __forceinline__ float h2f_hi(uint32_t p) {
    return __half2float(__ushort_as_half((unsigned short)(p >> 16)));
}
#define CP16(dst, src) \
    asm volatile("cp.async.cg.shared.global [%0], [%1], 16;" \
                 :: "r"(dst), "l"(src) : "memory")
#define CP_COMMIT() asm volatile("cp.async.commit_group;" ::: "memory")
#define CP_WAIT2()  asm volatile("cp.async.wait_group 2;" ::: "memory")

// ---------------------------------------------------------------------------
// fp32 -> (f16 hi, f16 lo) split, 4 elems/thread
// ---------------------------------------------------------------------------
__global__ __launch_bounds__(256) void conv_split_hl(
    const float* __restrict__ src, __half* __restrict__ h,
    __half* __restrict__ l, int n4)
{
    int i = blockIdx.x * 256 + threadIdx.x;
    if (i >= n4) return;
    float4 x = ((const float4*)src)[i];
    uint32_t p0 = pk2h(x.x, x.y), p1 = pk2h(x.z, x.w);
    float l0 = x.x - h2f_lo(p0);
    float l1 = x.y - h2f_hi(p0);
    float l2 = x.z - h2f_lo(p1);
    float l3 = x.w - h2f_hi(p1);
    uint2 hh; hh.x = p0; hh.y = p1;
    uint2 ll; ll.x = pk2h(l0, l1); ll.y = pk2h(l2, l3);
    ((uint2*)h)[i] = hh;
    ((uint2*)l)[i] = ll;
}

// fp32 -> f16 hi only (B-side operands), 4 elems/thread
__global__ __launch_bounds__(256) void conv_split_h(
    const float* __restrict__ src, __half* __restrict__ h, int n4)
{
    int i = blockIdx.x * 256 + threadIdx.x;
    if (i >= n4) return;
    float4 x = ((const float4*)src)[i];
    uint2 hh; hh.x = pk2h(x.x, x.y); hh.y = pk2h(x.z, x.w);
    ((uint2*)h)[i] = hh;
}

// ---------------------------------------------------------------------------
// Fused RoPE + split on Q/K columns (0..4095). Q cols get hi+lo, K hi only.
// ---------------------------------------------------------------------------
__global__ __launch_bounds__(256) void rope_split(
    const float* __restrict__ qkv, const float* __restrict__ cosb,
    const float* __restrict__ sinb,
    __half* __restrict__ qh, __half* __restrict__ ql)
{
    int idx = blockIdx.x * 256 + threadIdx.x;   // S_LEN * 1024
    int s = idx >> 10;
    int c = (idx & 1023) * 4;
    int d = c & 127;
    const float* row = qkv + (size_t)s * OPSZ;
    float4 x = *(const float4*)(row + c);
    if (d < 96) {
        float4 cc = *(const float4*)(cosb + s * 96 + d);
        float4 ss = *(const float4*)(sinb + s * 96 + d);
        if (d < 48) {
            float4 p = *(const float4*)(row + c + 48);
            x.x = x.x * cc.x - p.x * ss.x;
            x.y = x.y * cc.y - p.y * ss.y;
            x.z = x.z * cc.z - p.z * ss.z;
            x.w = x.w * cc.w - p.w * ss.w;
        } else {
            float4 p = *(const float4*)(row + c - 48);
            x.x = x.x * cc.x + p.x * ss.x;
            x.y = x.y * cc.y + p.y * ss.y;
            x.z = x.z * cc.z + p.z * ss.z;
            x.w = x.w * cc.w + p.w * ss.w;
        }
    }
    uint32_t p0 = pk2h(x.x, x.y), p1 = pk2h(x.z, x.w);
    size_t o = ((size_t)s * QK_COLS + c) >> 2;
    uint2 hh; hh.x = p0; hh.y = p1;
    ((uint2*)qh)[o] = hh;
    if (c < HID) {                      // lo needed only for Q (A-side)
        float l0 = x.x - h2f_lo(p0);
        float l1 = x.y - h2f_hi(p0);
        float l2 = x.z - h2f_lo(p1);
        float l3 = x.w - h2f_hi(p1);
        uint2 ll; ll.x = pk2h(l0, l1); ll.y = pk2h(l2, l3);
        ((uint2*)ql)[o] = ll;
    }
}

// ---------------------------------------------------------------------------
// V transpose + split (hi only): vT[kv*HD+d][s] = qkv[s][4096+kv*HD+d]
// ---------------------------------------------------------------------------
__global__ __launch_bounds__(256) void vsplit_T(
    const float* __restrict__ qkv, __half* __restrict__ vh)
{
    __shared__ float tile[32][33];
    const int t0 = blockIdx.x * 32;
    const int s0 = blockIdx.y * 32;
    const int tx = threadIdx.x, ty = threadIdx.y;   // (32, 8)
#pragma unroll
    for (int j = 0; j < 4; j++)
        tile[ty + 8 * j][tx] =
            qkv[(size_t)(s0 + ty + 8 * j) * OPSZ + 4096 + t0 + tx];
    __syncthreads();
#pragma unroll
    for (int j = 0; j < 4; j++) {
        float v = tile[tx][ty + 8 * j];
        vh[(size_t)(t0 + ty + 8 * j) * S_LEN + s0 + tx] = __float2half_rn(v);
    }
}

// ---------------------------------------------------------------------------
// Generic NT GEMM, fp16: C = alpha * (Ah [+Al]) [M,K] * Bh[N,K]^T
// Al term applied only for tiles with col0 < nloCols (per-tile term count).
// 128x128 tile, 512 threads (16 warps, warp tile 32x32), KC=32,
// 4-stage cp.async pipeline, 80B SMEM row pitch.
// flags: 1 = causal tile skip, 2 = K limited to row0+128,
//        4 = f16 split output (hi to Ch; lo to Cl only if !(flags&8)).
// ---------------------------------------------------------------------------
#define KC 32
#define TILE80 10240u              // 128 rows * 80 B
#define STAGE_B (3u * TILE80)      // Ah Al Bh = 30720
#define NSTAGE  4
#define GEMM_SMEM (NSTAGE * STAGE_B)   // 122880

__global__ __launch_bounds__(512) void gemm_f16(
    const __half* __restrict__ Ah, const __half* __restrict__ Al,
    int lda, long long sAz,
    const __half* __restrict__ Bh, int ldb, long long sBz, int kvdiv,
    float* __restrict__ Cf, __half* __restrict__ Ch,
    __half* __restrict__ Cl, int ldc, long long sCz,
    int K, float alpha, int flags, int nloCols)
{
    const int row0 = blockIdx.y << 7;
    const int col0 = blockIdx.x << 7;
    if ((flags & 1) && col0 > row0) return;
    const bool useAl = (col0 < nloCols);
    const int z = blockIdx.z;
    const size_t za = (size_t)z * sAz;
    const size_t zb = (size_t)(z / kvdiv) * sBz;
    const size_t zc = (size_t)z * sCz;
    Ah += za; Al += za; Bh += zb;
    const int Keff = (flags & 2) ? ((K < row0 + 128) ? K : row0 + 128) : K;
    const int nCh  = Keff >> 5;

    extern __shared__ char smem[];
    const uint32_t base = smem_u32(smem);

    const int tid  = threadIdx.x;
    const int warp = tid >> 5;
    const int lane = tid & 31;
    const int wm   = warp >> 2;      // 0..3
    const int wn   = warp & 3;       // 0..3

    // producer mapping: row = tid>>2 (0..127), 16B chunk = tid&3
    const int prow = tid >> 2;
    const int pq   = tid & 3;
    const uint32_t pst = (uint32_t)prow * 80u + (uint32_t)pq * 16u;
    const __half* pAh = Ah + (size_t)(row0 + prow) * lda + pq * 8;
    const __half* pAl = Al + (size_t)(row0 + prow) * lda + pq * 8;
    const __half* pBh = Bh + (size_t)(col0 + prow) * ldb + pq * 8;

    // prologue: stages 0..2 (nCh >= 4 for every launch in this problem)
#pragma unroll
    for (int s = 0; s < NSTAGE - 1; s++) {
        const int kO = s * KC;
        const uint32_t st = base + (uint32_t)s * STAGE_B;
        CP16(st + pst,               pAh + kO);
        if (useAl) CP16(st + TILE80 + pst, pAl + kO);
        CP16(st + 2u * TILE80 + pst, pBh + kO);
        CP_COMMIT();
    }

    // acc[mt][g] = n-subtile 2g, acc2[mt][g] = n-subtile 2g+1
    float acc [2][2][4];
    float acc2[2][2][4];
#pragma unroll
    for (int mt = 0; mt < 2; mt++)
#pragma unroll
        for (int g = 0; g < 2; g++)
#pragma unroll
            for (int r = 0; r < 4; r++) { acc[mt][g][r] = 0.f; acc2[mt][g][r] = 0.f; }

    const uint32_t aRow  = (uint32_t)(wm * 32 + (lane & 15));
    const uint32_t aSlot = (uint32_t)(lane >> 4);
    const uint32_t bRow  = (uint32_t)(wn * 32 + (lane & 7) + ((lane >> 4) << 3));
    const uint32_t bSlot = (uint32_t)((lane >> 3) & 1);

    for (int i = 0; i < nCh; i++) {
        CP_WAIT2();                 // chunk i landed
        __syncthreads();            // all warps done with the stage being refilled
        if (i + NSTAGE - 1 < nCh) {
            const int kO = (i + NSTAGE - 1) * KC;
            const uint32_t st =
                base + (uint32_t)((i + NSTAGE - 1) & (NSTAGE - 1)) * STAGE_B;
            CP16(st + pst,               pAh + kO);
            if (useAl) CP16(st + TILE80 + pst, pAl + kO);
            CP16(st + 2u * TILE80 + pst, pBh + kO);
        }
        CP_COMMIT();

        const uint32_t buf = base + (uint32_t)(i & (NSTAGE - 1)) * STAGE_B;
#pragma unroll
        for (int s = 0; s < 2; s++) {
            uint32_t a[2][4];       // Ah, later overwritten by Al
            uint32_t b2[2][4];      // Bh (two subtiles per group)
            // phase 1: Ah x Bh
#pragma unroll
            for (int mt = 0; mt < 2; mt++)
                ldm4(a[mt], buf + (aRow + (uint32_t)(mt * 16)) * 80u
                                + (2u * s + aSlot) * 16u);
#pragma unroll
            for (int g = 0; g < 2; g++)
                ldm4(b2[g], buf + 2u * TILE80
                                + (bRow + (uint32_t)(g * 16)) * 80u
                                + (2u * s + bSlot) * 16u);
#pragma unroll
            for (int mt = 0; mt < 2; mt++)
#pragma unroll
                for (int g = 0; g < 2; g++) {
                    mma16816(acc [mt][g], a[mt], b2[g]);
                    mma16816(acc2[mt][g], a[mt], b2[g] + 2);
                }
            // phase 2: Al x Bh (only when this tile carries the lo term)
            if (useAl) {
#pragma unroll
                for (int mt = 0; mt < 2; mt++)
                    ldm4(a[mt], buf + TILE80
                                    + (aRow + (uint32_t)(mt * 16)) * 80u
                                    + (2u * s + aSlot) * 16u);
#pragma unroll
                for (int mt = 0; mt < 2; mt++)
#pragma unroll
                    for (int g = 0; g < 2; g++) {
                        mma16816(acc [mt][g], a[mt], b2[g]);
                        mma16816(acc2[mt][g], a[mt], b2[g] + 2);
                    }
            }
        }
    }

    // epilogue: group g covers n-subtiles {2g (acc), 2g+1 (acc2)}
#pragma unroll
    for (int mt = 0; mt < 2; mt++) {
        const int rbase = row0 + wm * 32 + mt * 16 + (lane >> 2);
#pragma unroll
        for (int g = 0; g < 2; g++) {
#pragma unroll
            for (int half = 0; half < 2; half++) {
                const float* a4 = half ? acc2[mt][g] : acc[mt][g];
                const int nt = 2 * g + half;
                const int cbase = col0 + wn * 32 + nt * 8 + (lane & 3) * 2;
                float v00 = alpha * a4[0];
                float v01 = alpha * a4[1];
                float v10 = alpha * a4[2];
                float v11 = alpha * a4[3];
                if (flags & 4) {
                    uint32_t h0 = pk2h(v00, v01);
                    uint32_t h1 = pk2h(v10, v11);
                    *(uint32_t*)(Ch + zc + (size_t)rbase * ldc + cbase)       = h0;
                    *(uint32_t*)(Ch + zc + (size_t)(rbase + 8) * ldc + cbase) = h1;
                    if (!(flags & 8)) {
                        uint32_t l0 = pk2h(v00 - h2f_lo(h0), v01 - h2f_hi(h0));
                        uint32_t l1 = pk2h(v10 - h2f_lo(h1), v11 - h2f_hi(h1));
                        *(uint32_t*)(Cl + zc + (size_t)rbase * ldc + cbase)       = l0;
                        *(uint32_t*)(Cl + zc + (size_t)(rbase + 8) * ldc + cbase) = l1;
                    }
                } else {
                    float2 v0; v0.x = v00; v0.y = v01;
                    float2 v1; v1.x = v10; v1.y = v11;
                    *(float2*)(Cf + zc + (size_t)rbase * ldc + cbase)       = v0;
                    *(float2*)(Cf + zc + (size_t)(rbase + 8) * ldc + cbase) = v1;
                }
            }
        }
    }
}

// ---------------------------------------------------------------------------
// Causal softmax in place; emits f16 P (hi only) up to the 128-row block end.
// ---------------------------------------------------------------------------
__global__ __launch_bounds__(256) void softmax_causal(
    float* __restrict__ attn, __half* __restrict__ Ph)
{
    const int r = blockIdx.x;
    const int h = blockIdx.y;
    const size_t ro = ((size_t)h * S_LEN + r) * S_LEN;
    float* row = attn + ro;
    const int nv  = r + 1;
    const int blockend = ((r >> 7) + 1) << 7;   // end of diagonal 128-block
    const int tid = threadIdx.x;

    float v[8];
    float mx = -1e30f;
#pragma unroll
    for (int i = 0; i < 8; i++) {
        int c = tid + i * 256;
        v[i] = (c < nv) ? row[c] : -1e30f;
        mx = fmaxf(mx, v[i]);
    }

    __shared__ float red[256];
    red[tid] = mx;
    __syncthreads();
#pragma unroll
    for (int s2 = 128; s2 > 0; s2 >>= 1) {
        if (tid < s2) red[tid] = fmaxf(red[tid], red[tid + s2]);
        __syncthreads();
    }
    mx = red[0];
    __syncthreads();

    float sum = 0.f;
#pragma unroll
    for (int i = 0; i < 8; i++) {
        int c = tid + i * 256;
        v[i] = (c < nv) ? expf(v[i] - mx) : 0.f;
        sum += v[i];
    }
    red[tid] = sum;
    __syncthreads();
#pragma unroll
    for (int s2 = 128; s2 > 0; s2 >>= 1) {
        if (tid < s2) red[tid] += red[tid + s2];
        __syncthreads();
    }
    const float inv = 1.f / red[0];

#pragma unroll
    for (int i = 0; i < 8; i++) {
        int c = tid + i * 256;
        float val = v[i] * inv;
        row[c] = val;
        if (c < blockend) Ph[ro + c] = __float2half_rn(val);
    }
}

// ---------------------------------------------------------------------------
// Launch
// Inputs: hidden_states, cos, sin, attention_mask, w_qkv, w_o
// Output: [out (1,2048,3072)] ++ [attn_weights (1,24,2048,2048)]
// ---------------------------------------------------------------------------
extern "C" void kernel_launch(void* const* d_in, const int* in_sizes, int n_in,
                              void* d_out, int out_size)
{
    const float* hidden = (const float*)d_in[0];
    const float* cosb   = (const float*)d_in[1];
    const float* sinb   = (const float*)d_in[2];
    const float* wqkv   = (const float*)d_in[4];
    const float* wo     = (const float*)d_in[5];

    float* out  = (float*)d_out;
    float* attn = out + (size_t)S_LEN * HID;

    float* qkv;
    __half *hidh, *hidl, *wqkvh, *woh;
    __half *qkh, *qkl, *vTh, *Ph, *aoh;
    cudaGetSymbolAddress((void**)&qkv,   g_qkv);
    cudaGetSymbolAddress((void**)&hidh,  g_hidh);
    cudaGetSymbolAddress((void**)&hidl,  g_hidl);
    cudaGetSymbolAddress((void**)&wqkvh, g_wqkvh);
    cudaGetSymbolAddress((void**)&woh,   g_woh);
    cudaGetSymbolAddress((void**)&qkh,   g_qkh);
    cudaGetSymbolAddress((void**)&qkl,   g_qkl);
    cudaGetSymbolAddress((void**)&vTh,   g_vTh);
    cudaGetSymbolAddress((void**)&Ph,    g_Ph);
    cudaGetSymbolAddress((void**)&aoh,   g_aoh);

    cudaFuncSetAttribute(gemm_f16, cudaFuncAttributeMaxDynamicSharedMemorySize,
                         GEMM_SMEM);

    // one-time side stream + events for overlapping the w_o split
    static cudaStream_t s2 = nullptr;
    static cudaEvent_t evF = nullptr, evJ = nullptr;
    if (!s2) {
        cudaStreamCreateWithFlags(&s2, cudaStreamNonBlocking);
        cudaEventCreateWithFlags(&evF, cudaEventDisableTiming);
        cudaEventCreateWithFlags(&evJ, cudaEventDisableTiming);
    }

    // fork: w_o split runs on s2, overlapped with main-stream work
    cudaEventRecord(evF, 0);
    cudaStreamWaitEvent(s2, evF, 0);
    conv_split_h<<<(HID * HID / 4 + 255) / 256, 256, 0, s2>>>(
        wo, woh, HID * HID / 4);
    cudaEventRecord(evJ, s2);

    // 0. operand splits needed before QKV (main stream)
    conv_split_hl<<<(S_LEN * HID / 4 + 255) / 256, 256>>>(hidden, hidh, hidl,
                                                          S_LEN * HID / 4);
    conv_split_h<<<(OPSZ * HID / 4 + 255) / 256, 256>>>(wqkv, wqkvh,
                                                        OPSZ * HID / 4);

    // 1. qkv = hidden @ w_qkv^T   (2048 x 5120, K=3072), fp32 out
    //    Q tiles (col0 < 3072): hi+lo A; K/V tiles: hi-only A.
    gemm_f16<<<dim3(OPSZ / 128, S_LEN / 128, 1), 512, GEMM_SMEM>>>(
        hidh, hidl, HID, 0, wqkvh, HID, 0, 1,
        qkv, nullptr, nullptr, OPSZ, 0, HID, 1.0f, 0, HID);

    // 2. RoPE + split Q(hi/lo)/K(hi);  3. transpose + split V (hi)
    rope_split<<<S_LEN * 1024 / 256, 256>>>(qkv, cosb, sinb, qkh, qkl);
    vsplit_T<<<dim3((NKV * HD) / 32, S_LEN / 32), dim3(32, 8)>>>(qkv, vTh);

    // 4. scores = Q K^T * scale (causal tiles only) -> attn fp32 (2-term A)
    gemm_f16<<<dim3(S_LEN / 128, S_LEN / 128, NH), 512, GEMM_SMEM>>>(
        qkh, qkl, QK_COLS, HD,
        qkh + HID, QK_COLS, HD, 3,
        attn, nullptr, nullptr, S_LEN, (long long)S_LEN * S_LEN,
        HD, SCALING, 1, 1 << 30);

    // 5. softmax in place + P hi emit (block-limited)
    softmax_causal<<<dim3(S_LEN, NH), 256>>>(attn, Ph);

    // 6. ao(hi) = P @ V   (K limited to row0+128; P hi-only -> 1 term)
    gemm_f16<<<dim3(HD / 128, S_LEN / 128, NH), 512, GEMM_SMEM>>>(
        Ph, Ph, S_LEN, (long long)S_LEN * S_LEN,
        vTh, S_LEN, (long long)HD * S_LEN, 3,
        nullptr, aoh, nullptr, HID, HD,
        S_LEN, 1.0f, 2 | 4 | 8, 0);

    // join: w_o split must be done before the out-proj GEMM
    cudaStreamWaitEvent(0, evJ, 0);

    // 7. out = ao @ w_o^T   (2048 x 3072, K=3072), fp32 out (1-term)
    gemm_f16<<<dim3(HID / 128, S_LEN / 128, 1), 512, GEMM_SMEM>>>(
        aoh, aoh, HID, 0, woh, HID, 0, 1,
        out, nullptr, nullptr, HID, 0, HID, 1.0f, 0, 0);
}